// round 3
// baseline (speedup 1.0000x reference)
#include <cuda_runtime.h>

#define NA 100000
#define NE 200000
#define NF 100000
#define DD 128
#define NEDGE 400000

// ---------------- scratch (device globals: allocation-free) ----------------
__device__ float g_agg[(size_t)NE * DD];   // 102.4 MB, max dst count
__device__ int   g_cnt[NE];
__device__ int   g_rowstart[NE];
__device__ int   g_cursor[NE];
__device__ int   g_edge_src[NEDGE];
__device__ int   g_bsums[64];

// ---------------- CSR build ----------------
__global__ void k_zero_cnt(int n) {
    int i = blockIdx.x * blockDim.x + threadIdx.x;
    if (i < n) g_cnt[i] = 0;
}

__global__ void k_hist(const int* __restrict__ di, int ne) {
    int e = blockIdx.x * blockDim.x + threadIdx.x;
    if (e < ne) atomicAdd(&g_cnt[di[e]], 1);
}

// block-local exclusive scan over 4096-element chunks
__global__ void k_scan1(int n) {
    __shared__ int s[1024];
    int t = threadIdx.x;
    int base = blockIdx.x * 4096;
    int v[4];
    int sum = 0;
#pragma unroll
    for (int j = 0; j < 4; j++) {
        int idx = base + t * 4 + j;
        v[j] = (idx < n) ? g_cnt[idx] : 0;
        sum += v[j];
    }
    s[t] = sum;
    __syncthreads();
    for (int off = 1; off < 1024; off <<= 1) {
        int x = (t >= off) ? s[t - off] : 0;
        __syncthreads();
        if (t >= off) s[t] += x;
        __syncthreads();
    }
    int excl = s[t] - sum;
    if (t == 1023) g_bsums[blockIdx.x] = s[1023];
    int run = excl;
#pragma unroll
    for (int j = 0; j < 4; j++) {
        int idx = base + t * 4 + j;
        if (idx < n) g_rowstart[idx] = run;
        run += v[j];
    }
}

__global__ void k_scan2(int nb) {
    if (threadIdx.x == 0 && blockIdx.x == 0) {
        int acc = 0;
        for (int i = 0; i < nb; i++) { int v = g_bsums[i]; g_bsums[i] = acc; acc += v; }
    }
}

__global__ void k_scan3(int n) {
    int i = blockIdx.x * blockDim.x + threadIdx.x;
    if (i < n) {
        int r = g_rowstart[i] + g_bsums[i >> 12];
        g_rowstart[i] = r;
        g_cursor[i] = r;
    }
}

__global__ void k_scatter(const int* __restrict__ si, const int* __restrict__ di, int ne) {
    int e = blockIdx.x * blockDim.x + threadIdx.x;
    if (e < ne) {
        int d = di[e];
        int p = atomicAdd(&g_cursor[d], 1);
        g_edge_src[p] = si[e];
    }
}

// ---------------- pull-style mean aggregation: one warp per dst row ----------------
__global__ void k_aggregate(const float* __restrict__ xsrc, int n_dst) {
    int w = (blockIdx.x * blockDim.x + threadIdx.x) >> 5;
    int lane = threadIdx.x & 31;
    if (w >= n_dst) return;
    int start = g_rowstart[w];
    int c = g_cnt[w];
    float4 acc = make_float4(0.f, 0.f, 0.f, 0.f);
    for (int j = 0; j < c; j++) {
        int sidx = __ldg(&g_edge_src[start + j]);
        float4 vv = __ldg((const float4*)(xsrc + (size_t)sidx * DD) + lane);
        acc.x += vv.x; acc.y += vv.y; acc.z += vv.z; acc.w += vv.w;
    }
    float inv = 1.0f / (float)(c > 1 ? c : 1);
    float4 o = make_float4(acc.x * inv, acc.y * inv, acc.z * inv, acc.w * inv);
    *((float4*)(g_agg + (size_t)w * DD) + lane) = o;
}

// ---------------- fused GEMM (K=256: [x_dst|agg] @ [wl|wr]^T) + bias + L2 norm + accum ----------------
__device__ __forceinline__ void load_tile_regs(
    const float* __restrict__ xd,
    const float* __restrict__ wl, const float* __restrict__ wr,
    int kt, int m0, int n_dst, int lr, int lh,
    float4 ra[2], float4 rb[2])
{
    int klocal = (kt & 7) * 16 + lh * 8;
    const float* asrc = (kt < 8) ? xd : g_agg;
    const float* bsrc = (kt < 8) ? wl : wr;
    int m = m0 + lr;
    if (m < n_dst) {
        const float4* p = (const float4*)(asrc + (size_t)m * DD + klocal);
        ra[0] = p[0]; ra[1] = p[1];
    } else {
        ra[0] = make_float4(0.f, 0.f, 0.f, 0.f);
        ra[1] = make_float4(0.f, 0.f, 0.f, 0.f);
    }
    const float4* q = (const float4*)(bsrc + lr * DD + klocal);
    rb[0] = q[0]; rb[1] = q[1];
}

__device__ __forceinline__ void store_tile_smem(
    float (*sA)[128], float (*sB)[128], int lr, int lh,
    const float4 ra[2], const float4 rb[2])
{
    float av[8] = {ra[0].x, ra[0].y, ra[0].z, ra[0].w, ra[1].x, ra[1].y, ra[1].z, ra[1].w};
    float bv[8] = {rb[0].x, rb[0].y, rb[0].z, rb[0].w, rb[1].x, rb[1].y, rb[1].z, rb[1].w};
#pragma unroll
    for (int j = 0; j < 8; j++) {
        sA[lh * 8 + j][lr] = av[j];
        sB[lh * 8 + j][lr] = bv[j];
    }
}

__global__ __launch_bounds__(256)
void k_sage_gemm(const float* __restrict__ xd,
                 const float* __restrict__ wl, const float* __restrict__ wr,
                 const float* __restrict__ bias,
                 float* __restrict__ out, int n_dst, int accumulate)
{
    __shared__ float sA[2][16][128];
    __shared__ float sB[2][16][128];

    int tid = threadIdx.x;
    int tx = tid & 15;    // output column group (8 cols)
    int ty = tid >> 4;    // output row group (8 rows)
    int m0 = blockIdx.x * 128;
    int lr = tid >> 1;    // loader row (0..127)
    int lh = tid & 1;     // loader half (8 floats each)

    float acc[8][8];
#pragma unroll
    for (int i = 0; i < 8; i++)
#pragma unroll
        for (int j = 0; j < 8; j++) acc[i][j] = 0.f;

    float4 ra[2], rb[2];
    load_tile_regs(xd, wl, wr, 0, m0, n_dst, lr, lh, ra, rb);
    store_tile_smem(sA[0], sB[0], lr, lh, ra, rb);
    __syncthreads();

    for (int kt = 0; kt < 16; kt++) {
        int cur = kt & 1;
        if (kt < 15) load_tile_regs(xd, wl, wr, kt + 1, m0, n_dst, lr, lh, ra, rb);
#pragma unroll
        for (int kk = 0; kk < 16; kk++) {
            float4 a0 = *(const float4*)&sA[cur][kk][ty * 8];
            float4 a1 = *(const float4*)&sA[cur][kk][ty * 8 + 4];
            float4 b0 = *(const float4*)&sB[cur][kk][tx * 8];
            float4 b1 = *(const float4*)&sB[cur][kk][tx * 8 + 4];
            float av[8] = {a0.x, a0.y, a0.z, a0.w, a1.x, a1.y, a1.z, a1.w};
            float bv[8] = {b0.x, b0.y, b0.z, b0.w, b1.x, b1.y, b1.z, b1.w};
#pragma unroll
            for (int i = 0; i < 8; i++)
#pragma unroll
                for (int j = 0; j < 8; j++)
                    acc[i][j] += av[i] * bv[j];
        }
        if (kt < 15) {
            store_tile_smem(sA[cur ^ 1], sB[cur ^ 1], lr, lh, ra, rb);
            __syncthreads();
        }
    }

    // epilogue: bias, L2 normalize per row (row spread over 16 tx lanes), accumulate
    float bv[8];
#pragma unroll
    for (int j = 0; j < 8; j++) bv[j] = __ldg(&bias[tx * 8 + j]);

#pragma unroll
    for (int i = 0; i < 8; i++) {
        int m = m0 + ty * 8 + i;
        float v[8];
        float ss = 0.f;
#pragma unroll
        for (int j = 0; j < 8; j++) {
            v[j] = acc[i][j] + bv[j];
            ss += v[j] * v[j];
        }
        // reduce across the 16 lanes holding this row
#pragma unroll
        for (int off = 8; off >= 1; off >>= 1)
            ss += __shfl_xor_sync(0xFFFFFFFFu, ss, off, 16);
        float nrm = sqrtf(ss);
        float scale = 1.0f / fmaxf(nrm, 1e-12f);
        if (m < n_dst) {
            float4* op = (float4*)(out + (size_t)m * DD + tx * 8);
            float4 o0 = make_float4(v[0] * scale, v[1] * scale, v[2] * scale, v[3] * scale);
            float4 o1 = make_float4(v[4] * scale, v[5] * scale, v[6] * scale, v[7] * scale);
            if (accumulate) {
                float4 e0 = op[0], e1 = op[1];
                o0.x += e0.x; o0.y += e0.y; o0.z += e0.z; o0.w += e0.w;
                o1.x += e1.x; o1.y += e1.y; o1.z += e1.z; o1.w += e1.w;
            }
            op[0] = o0;
            op[1] = o1;
        }
    }
}

// ---------------- per-edge-type pipeline ----------------
static void run_type(const float* xsrc, const float* xdst,
                     const int* si, const int* di, int n_dst,
                     const float* wl, const float* bias, const float* wr,
                     float* out_sec, int accumulate)
{
    const int tb = 256;
    k_zero_cnt<<<(n_dst + tb - 1) / tb, tb>>>(n_dst);
    k_hist<<<(NEDGE + tb - 1) / tb, tb>>>(di, NEDGE);
    int nb = (n_dst + 4095) / 4096;
    k_scan1<<<nb, 1024>>>(n_dst);
    k_scan2<<<1, 32>>>(nb);
    k_scan3<<<(n_dst + tb - 1) / tb, tb>>>(n_dst);
    k_scatter<<<(NEDGE + tb - 1) / tb, tb>>>(si, di, NEDGE);
    k_aggregate<<<(n_dst * 32 + tb - 1) / tb, tb>>>(xsrc, n_dst);
    k_sage_gemm<<<(n_dst + 127) / 128, 256>>>(xdst, wl, wr, bias, out_sec, n_dst, accumulate);
}

extern "C" void kernel_launch(void* const* d_in, const int* in_sizes, int n_in,
                              void* d_out, int out_size)
{
    const float* xa = (const float*)d_in[0];
    const float* xe = (const float*)d_in[1];
    const float* xf = (const float*)d_in[2];

    const int* si[5];
    const int* di[5];
    for (int t = 0; t < 5; t++) {
        si[t] = (const int*)d_in[3 + 2 * t];
        di[t] = (const int*)d_in[4 + 2 * t];
    }
    const float* wl[5];
    const float* bb[5];
    const float* wr[5];
    for (int t = 0; t < 5; t++) {
        wl[t] = (const float*)d_in[13 + 3 * t];
        bb[t] = (const float*)d_in[14 + 3 * t];
        wr[t] = (const float*)d_in[15 + 3 * t];
    }

    float* out = (float*)d_out;
    float* out_article = out;
    float* out_entity  = out + (size_t)NA * DD;
    float* out_fact    = out + (size_t)(NA + NE) * DD;

    // EDGE_TYPES: (article->entity), (article->fact), (entity->article),
    //             (entity->fact), (fact->entity)
    run_type(xa, xe, si[0], di[0], NE, wl[0], bb[0], wr[0], out_entity, 0);
    run_type(xa, xf, si[1], di[1], NF, wl[1], bb[1], wr[1], out_fact, 0);
    run_type(xe, xa, si[2], di[2], NA, wl[2], bb[2], wr[2], out_article, 0);
    run_type(xe, xf, si[3], di[3], NF, wl[3], bb[3], wr[3], out_fact, 1);
    run_type(xf, xe, si[4], di[4], NE, wl[4], bb[4], wr[4], out_entity, 1);
}

// round 4
// speedup vs baseline: 1.8230x; 1.8230x over previous
#include <cuda_runtime.h>
#include <cstdint>

#define NA 100000
#define NE 200000
#define NF 100000
#define DD 128
#define NEDGE 400000

// ---------------- scratch (device globals: allocation-free) ----------------
__device__ float g_agg[(size_t)NE * DD];   // 102.4 MB, max dst count
__device__ int   g_cnt[NE];
__device__ int   g_rowstart[NE];
__device__ int   g_cursor[NE];
__device__ int   g_edge_src[NEDGE];
__device__ int   g_bsums[64];

// ---------------- CSR build ----------------
__global__ void k_zero_cnt(int n) {
    int i = blockIdx.x * blockDim.x + threadIdx.x;
    if (i < n) g_cnt[i] = 0;
}

__global__ void k_hist(const int* __restrict__ di, int ne) {
    int e = blockIdx.x * blockDim.x + threadIdx.x;
    if (e < ne) atomicAdd(&g_cnt[di[e]], 1);
}

__global__ void k_scan1(int n) {
    __shared__ int s[1024];
    int t = threadIdx.x;
    int base = blockIdx.x * 4096;
    int v[4];
    int sum = 0;
#pragma unroll
    for (int j = 0; j < 4; j++) {
        int idx = base + t * 4 + j;
        v[j] = (idx < n) ? g_cnt[idx] : 0;
        sum += v[j];
    }
    s[t] = sum;
    __syncthreads();
    for (int off = 1; off < 1024; off <<= 1) {
        int x = (t >= off) ? s[t - off] : 0;
        __syncthreads();
        if (t >= off) s[t] += x;
        __syncthreads();
    }
    int excl = s[t] - sum;
    if (t == 1023) g_bsums[blockIdx.x] = s[1023];
    int run = excl;
#pragma unroll
    for (int j = 0; j < 4; j++) {
        int idx = base + t * 4 + j;
        if (idx < n) g_rowstart[idx] = run;
        run += v[j];
    }
}

__global__ void k_scan2(int nb) {
    if (threadIdx.x == 0 && blockIdx.x == 0) {
        int acc = 0;
        for (int i = 0; i < nb; i++) { int v = g_bsums[i]; g_bsums[i] = acc; acc += v; }
    }
}

__global__ void k_scan3(int n) {
    int i = blockIdx.x * blockDim.x + threadIdx.x;
    if (i < n) {
        int r = g_rowstart[i] + g_bsums[i >> 12];
        g_rowstart[i] = r;
        g_cursor[i] = r;
    }
}

__global__ void k_scatter(const int* __restrict__ si, const int* __restrict__ di, int ne) {
    int e = blockIdx.x * blockDim.x + threadIdx.x;
    if (e < ne) {
        int d = di[e];
        int p = atomicAdd(&g_cursor[d], 1);
        g_edge_src[p] = si[e];
    }
}

// ---------------- pull-style mean aggregation: one warp per dst row ----------------
__global__ void k_aggregate(const float* __restrict__ xsrc, int n_dst) {
    int w = (blockIdx.x * blockDim.x + threadIdx.x) >> 5;
    int lane = threadIdx.x & 31;
    if (w >= n_dst) return;
    int start = g_rowstart[w];
    int c = g_cnt[w];
    float4 acc = make_float4(0.f, 0.f, 0.f, 0.f);
    for (int j = 0; j < c; j++) {
        int sidx = __ldg(&g_edge_src[start + j]);
        float4 vv = __ldg((const float4*)(xsrc + (size_t)sidx * DD) + lane);
        acc.x += vv.x; acc.y += vv.y; acc.z += vv.z; acc.w += vv.w;
    }
    float inv = 1.0f / (float)(c > 1 ? c : 1);
    float4 o = make_float4(acc.x * inv, acc.y * inv, acc.z * inv, acc.w * inv);
    *((float4*)(g_agg + (size_t)w * DD) + lane) = o;
}

// ---------------- TF32 tensor-core fused GEMM ----------------
// out[m][n] = normalize( [x_dst|agg][m][0:256] @ [wl|wr][n][0:256]^T + b[n] )
// mma.m16n8k8: A operand = W tile (n-major), B operand = X tile (m-major).

__device__ __forceinline__ uint32_t f2tf32(float f) {
    uint32_t u;
    asm volatile("cvt.rna.tf32.f32 %0, %1;" : "=r"(u) : "f"(f));
    return u;
}

#define SROW 20   // smem row stride (words): 20*g mod 32 covers all banks -> conflict-free frags

__global__ __launch_bounds__(256, 2)
void k_sage_gemm_tf32(const float* __restrict__ xd,
                      const float* __restrict__ wl, const float* __restrict__ wr,
                      const float* __restrict__ bias,
                      float* __restrict__ out, int n_dst, int accumulate)
{
    __shared__ float sX[2][128 * SROW];
    __shared__ float sW[2][128 * SROW];
    __shared__ float sSS[128];

    const int tid = threadIdx.x;
    const int lane = tid & 31;
    const int warpId = tid >> 5;
    const int warpN = warpId & 1;       // 2 tiles of 64 n
    const int warpM = warpId >> 1;      // 4 tiles of 32 m
    const int g = lane >> 2;            // 0..7
    const int tg = lane & 3;            // 0..3
    const int m0 = blockIdx.x * 128;

    // loader mapping: row = tid>>1 (0..127), half = tid&1 (8 floats each)
    const int lrow = tid >> 1;
    const int lhalf = tid & 1;

    float c[4][4][4];                   // [nt][mt][r]
#pragma unroll
    for (int a = 0; a < 4; a++)
#pragma unroll
        for (int b = 0; b < 4; b++)
#pragma unroll
            for (int r = 0; r < 4; r++) c[a][b][r] = 0.f;

    float4 ra[2], rb[2];

    auto load_regs = [&](int kt) {
        const float* as = (kt < 8) ? xd : g_agg;
        const float* bs = (kt < 8) ? wl : wr;
        int klocal = (kt & 7) * 16 + lhalf * 8;
        int m = m0 + lrow;
        if (m < n_dst) {
            const float4* p = (const float4*)(as + (size_t)m * DD + klocal);
            ra[0] = p[0]; ra[1] = p[1];
        } else {
            ra[0] = make_float4(0.f, 0.f, 0.f, 0.f);
            ra[1] = make_float4(0.f, 0.f, 0.f, 0.f);
        }
        const float4* q = (const float4*)(bs + (size_t)lrow * DD + klocal);
        rb[0] = q[0]; rb[1] = q[1];
    };

    auto store_tile = [&](int buf) {
        int base = lrow * SROW + lhalf * 8;
        *(float4*)&sX[buf][base]     = ra[0];
        *(float4*)&sX[buf][base + 4] = ra[1];
        *(float4*)&sW[buf][base]     = rb[0];
        *(float4*)&sW[buf][base + 4] = rb[1];
    };

    load_regs(0);
    store_tile(0);
    __syncthreads();

    for (int kt = 0; kt < 16; kt++) {
        int cur = kt & 1;
        if (kt < 15) load_regs(kt + 1);

        const float* sXc = sX[cur];
        const float* sWc = sW[cur];

#pragma unroll
        for (int k0 = 0; k0 < 16; k0 += 8) {
            // B fragments (X tile): b0 = x[m][k0+tg], b1 = x[m][k0+tg+4], m = warpM*32+mt*8+g
            uint32_t Bf[4][2];
#pragma unroll
            for (int mt = 0; mt < 4; mt++) {
                int rx = (warpM * 32 + mt * 8 + g) * SROW + k0 + tg;
                Bf[mt][0] = f2tf32(sXc[rx]);
                Bf[mt][1] = f2tf32(sXc[rx + 4]);
            }
#pragma unroll
            for (int nt = 0; nt < 4; nt++) {
                int rw = (warpN * 64 + nt * 16 + g) * SROW + k0 + tg;
                uint32_t a0 = f2tf32(sWc[rw]);
                uint32_t a1 = f2tf32(sWc[rw + 8 * SROW]);
                uint32_t a2 = f2tf32(sWc[rw + 4]);
                uint32_t a3 = f2tf32(sWc[rw + 8 * SROW + 4]);
#pragma unroll
                for (int mt = 0; mt < 4; mt++) {
                    asm volatile(
                        "mma.sync.aligned.m16n8k8.row.col.f32.tf32.tf32.f32 "
                        "{%0,%1,%2,%3}, {%4,%5,%6,%7}, {%8,%9}, {%0,%1,%2,%3};\n"
                        : "+f"(c[nt][mt][0]), "+f"(c[nt][mt][1]),
                          "+f"(c[nt][mt][2]), "+f"(c[nt][mt][3])
                        : "r"(a0), "r"(a1), "r"(a2), "r"(a3),
                          "r"(Bf[mt][0]), "r"(Bf[mt][1]));
                }
            }
        }

        if (kt < 15) {
            store_tile(cur ^ 1);
            __syncthreads();
        }
    }

    // ---------------- epilogue: bias, per-row L2 norm, (accumulate,) store ----------------
    // lane holds out[n][m] with n = warpN*64 + nt*16 + g + (r>>1)*8,
    //                          m_local = warpM*32 + mt*8 + 2*tg + (r&1)
    float bias_v[4][2];
#pragma unroll
    for (int nt = 0; nt < 4; nt++) {
        int n = warpN * 64 + nt * 16 + g;
        bias_v[nt][0] = __ldg(&bias[n]);
        bias_v[nt][1] = __ldg(&bias[n + 8]);
    }
#pragma unroll
    for (int nt = 0; nt < 4; nt++)
#pragma unroll
        for (int mt = 0; mt < 4; mt++)
#pragma unroll
            for (int r = 0; r < 4; r++)
                c[nt][mt][r] += bias_v[nt][r >> 1];

    __syncthreads();
    if (tid < 128) sSS[tid] = 0.f;
    __syncthreads();

    // partial sum-of-squares per (mt, j): over this lane's 8 n values
    float ps[4][2];
#pragma unroll
    for (int mt = 0; mt < 4; mt++)
#pragma unroll
        for (int j = 0; j < 2; j++) {
            float s = 0.f;
#pragma unroll
            for (int nt = 0; nt < 4; nt++) {
                float v0 = c[nt][mt][j];
                float v1 = c[nt][mt][2 + j];
                s += v0 * v0 + v1 * v1;
            }
            // reduce over g (lane bits 2..4): lanes sharing (tg, j) hold the same m
            s += __shfl_xor_sync(0xFFFFFFFFu, s, 4);
            s += __shfl_xor_sync(0xFFFFFFFFu, s, 8);
            s += __shfl_xor_sync(0xFFFFFFFFu, s, 16);
            ps[mt][j] = s;
        }
    if (g == 0) {
#pragma unroll
        for (int mt = 0; mt < 4; mt++)
#pragma unroll
            for (int j = 0; j < 2; j++)
                atomicAdd(&sSS[warpM * 32 + mt * 8 + 2 * tg + j], ps[mt][j]);
    }
    __syncthreads();

#pragma unroll
    for (int mt = 0; mt < 4; mt++) {
#pragma unroll
        for (int j = 0; j < 2; j++) {
            int mloc = warpM * 32 + mt * 8 + 2 * tg + j;
            int m = m0 + mloc;
            if (m >= n_dst) continue;
            float nrm = sqrtf(sSS[mloc]);
            float scale = 1.0f / fmaxf(nrm, 1e-12f);
            float* orow = out + (size_t)m * DD;
#pragma unroll
            for (int nt = 0; nt < 4; nt++) {
#pragma unroll
                for (int h = 0; h < 2; h++) {
                    int n = warpN * 64 + nt * 16 + g + h * 8;
                    float v = c[nt][mt][2 * h + j] * scale;
                    if (accumulate) v += orow[n];
                    orow[n] = v;
                }
            }
        }
    }
}

// ---------------- per-edge-type pipeline ----------------
static void run_type(const float* xsrc, const float* xdst,
                     const int* si, const int* di, int n_dst,
                     const float* wl, const float* bias, const float* wr,
                     float* out_sec, int accumulate)
{
    const int tb = 256;
    k_zero_cnt<<<(n_dst + tb - 1) / tb, tb>>>(n_dst);
    k_hist<<<(NEDGE + tb - 1) / tb, tb>>>(di, NEDGE);
    int nb = (n_dst + 4095) / 4096;
    k_scan1<<<nb, 1024>>>(n_dst);
    k_scan2<<<1, 32>>>(nb);
    k_scan3<<<(n_dst + tb - 1) / tb, tb>>>(n_dst);
    k_scatter<<<(NEDGE + tb - 1) / tb, tb>>>(si, di, NEDGE);
    k_aggregate<<<(n_dst * 32 + tb - 1) / tb, tb>>>(xsrc, n_dst);
    k_sage_gemm_tf32<<<(n_dst + 127) / 128, 256>>>(xdst, wl, wr, bias, out_sec, n_dst, accumulate);
}

extern "C" void kernel_launch(void* const* d_in, const int* in_sizes, int n_in,
                              void* d_out, int out_size)
{
    const float* xa = (const float*)d_in[0];
    const float* xe = (const float*)d_in[1];
    const float* xf = (const float*)d_in[2];

    const int* si[5];
    const int* di[5];
    for (int t = 0; t < 5; t++) {
        si[t] = (const int*)d_in[3 + 2 * t];
        di[t] = (const int*)d_in[4 + 2 * t];
    }
    const float* wl[5];
    const float* bb[5];
    const float* wr[5];
    for (int t = 0; t < 5; t++) {
        wl[t] = (const float*)d_in[13 + 3 * t];
        bb[t] = (const float*)d_in[14 + 3 * t];
        wr[t] = (const float*)d_in[15 + 3 * t];
    }

    float* out = (float*)d_out;
    float* out_article = out;
    float* out_entity  = out + (size_t)NA * DD;
    float* out_fact    = out + (size_t)(NA + NE) * DD;

    run_type(xa, xe, si[0], di[0], NE, wl[0], bb[0], wr[0], out_entity, 0);
    run_type(xa, xf, si[1], di[1], NF, wl[1], bb[1], wr[1], out_fact, 0);
    run_type(xe, xa, si[2], di[2], NA, wl[2], bb[2], wr[2], out_article, 0);
    run_type(xe, xf, si[3], di[3], NF, wl[3], bb[3], wr[3], out_fact, 1);
    run_type(xf, xe, si[4], di[4], NE, wl[4], bb[4], wr[4], out_entity, 1);
}

// round 5
// speedup vs baseline: 2.2887x; 1.2554x over previous
#include <cuda_runtime.h>
#include <cuda_fp16.h>
#include <cstdint>

#define NA 100000
#define NE 200000
#define NF 100000
#define DD 128
#define NEDGE 400000
#define TOTDST 700000
#define TOTEDGE 2000000
#define TOTSRC 400000   // xa + xe + xf rows

// ---------------- scratch (device globals: allocation-free) ----------------
// fp16 copies stored as uint32 (half2) words
__device__ uint32_t g_xh32[(size_t)TOTSRC * 64];   // 102.4 MB  [xa|xe|xf] rows x 128 halves
__device__ uint32_t g_agg32[(size_t)TOTDST * 64];  // 179.2 MB  per-type dst sections
__device__ uint32_t g_wh32[5 * 2 * 8192];          // 5 types x {wl,wr} x 128x128 halves
__device__ int   g_cnt[TOTDST];
__device__ int   g_rowstart[TOTDST];
__device__ int   g_cursor[TOTDST];
__device__ int   g_edge_src[TOTEDGE];
__device__ int   g_bsums[256];

// ---------------- fp32 -> fp16 pre-pass ----------------
// x features: grid.y = 0..2 selects table
__global__ void k_tohalf_x(const float* __restrict__ xa, const float* __restrict__ xe,
                           const float* __restrict__ xf) {
    int y = blockIdx.y;
    const float* src = (y == 0) ? xa : (y == 1) ? xe : xf;
    int rows = (y == 1) ? NE : NA;          // NA == NF
    size_t dstoff = (y == 0) ? 0 : (y == 1) ? (size_t)NA * 32 : (size_t)(NA + NE) * 32;
    int n4 = rows * 32;                      // float4 count
    int i = blockIdx.x * 256 + threadIdx.x;
    if (i >= n4) return;
    float4 v = ((const float4*)src)[i];
    __half2 a = __floats2half2_rn(v.x, v.y);
    __half2 b = __floats2half2_rn(v.z, v.w);
    uint32_t* d = g_xh32 + dstoff * 2 + (size_t)i * 2;
    d[0] = *(uint32_t*)&a;
    d[1] = *(uint32_t*)&b;
}

// weights: grid.y = 0..9 in order wl0,wr0,wl1,wr1,...  each 128x128
__global__ void k_tohalf_w(const float* p0, const float* p1, const float* p2, const float* p3,
                           const float* p4, const float* p5, const float* p6, const float* p7,
                           const float* p8, const float* p9) {
    int y = blockIdx.y;
    const float* src = (y == 0) ? p0 : (y == 1) ? p1 : (y == 2) ? p2 : (y == 3) ? p3 :
                       (y == 4) ? p4 : (y == 5) ? p5 : (y == 6) ? p6 : (y == 7) ? p7 :
                       (y == 8) ? p8 : p9;
    int i = blockIdx.x * 256 + threadIdx.x;   // float4 index, 4096 per matrix
    if (i >= 4096) return;
    float4 v = ((const float4*)src)[i];
    __half2 a = __floats2half2_rn(v.x, v.y);
    __half2 b = __floats2half2_rn(v.z, v.w);
    uint32_t* d = g_wh32 + (size_t)y * 8192 + (size_t)i * 2;
    d[0] = *(uint32_t*)&a;
    d[1] = *(uint32_t*)&b;
}

// ---------------- batched CSR build (all 5 types, global dst ids) ----------------
__global__ void k_zero_cnt() {
    int i = blockIdx.x * blockDim.x + threadIdx.x;
    if (i < TOTDST) g_cnt[i] = 0;
}

__device__ __forceinline__ int dst_off_of(int t) {
    return (t == 0) ? 0 : (t == 1) ? 200000 : (t == 2) ? 300000 : (t == 3) ? 400000 : 500000;
}

__global__ void k_hist(const int* d0, const int* d1, const int* d2, const int* d3, const int* d4) {
    int e = blockIdx.x * 256 + threadIdx.x;
    if (e >= NEDGE) return;
    int t = blockIdx.y;
    const int* di = (t == 0) ? d0 : (t == 1) ? d1 : (t == 2) ? d2 : (t == 3) ? d3 : d4;
    atomicAdd(&g_cnt[dst_off_of(t) + di[e]], 1);
}

__global__ void k_scan1() {
    __shared__ int s[1024];
    int t = threadIdx.x;
    int base = blockIdx.x * 4096;
    int v[4];
    int sum = 0;
#pragma unroll
    for (int j = 0; j < 4; j++) {
        int idx = base + t * 4 + j;
        v[j] = (idx < TOTDST) ? g_cnt[idx] : 0;
        sum += v[j];
    }
    s[t] = sum;
    __syncthreads();
    for (int off = 1; off < 1024; off <<= 1) {
        int x = (t >= off) ? s[t - off] : 0;
        __syncthreads();
        if (t >= off) s[t] += x;
        __syncthreads();
    }
    int excl = s[t] - sum;
    if (t == 1023) g_bsums[blockIdx.x] = s[1023];
    int run = excl;
#pragma unroll
    for (int j = 0; j < 4; j++) {
        int idx = base + t * 4 + j;
        if (idx < TOTDST) g_rowstart[idx] = run;
        run += v[j];
    }
}

__global__ void k_scan2(int nb) {
    __shared__ int s[256];
    int t = threadIdx.x;
    int v = (t < nb) ? g_bsums[t] : 0;
    s[t] = v;
    __syncthreads();
    for (int off = 1; off < 256; off <<= 1) {
        int x = (t >= off) ? s[t - off] : 0;
        __syncthreads();
        s[t] += x;
        __syncthreads();
    }
    if (t < nb) g_bsums[t] = s[t] - v;   // exclusive
}

__global__ void k_scan3() {
    int i = blockIdx.x * blockDim.x + threadIdx.x;
    if (i < TOTDST) {
        int r = g_rowstart[i] + g_bsums[i >> 12];
        g_rowstart[i] = r;
        g_cursor[i] = r;
    }
}

__global__ void k_scatter(const int* s0, const int* s1, const int* s2, const int* s3, const int* s4,
                          const int* d0, const int* d1, const int* d2, const int* d3, const int* d4) {
    int e = blockIdx.x * 256 + threadIdx.x;
    if (e >= NEDGE) return;
    int t = blockIdx.y;
    const int* si = (t == 0) ? s0 : (t == 1) ? s1 : (t == 2) ? s2 : (t == 3) ? s3 : s4;
    const int* di = (t == 0) ? d0 : (t == 1) ? d1 : (t == 2) ? d2 : (t == 3) ? d3 : d4;
    int d = dst_off_of(t) + di[e];
    int p = atomicAdd(&g_cursor[d], 1);
    g_edge_src[p] = si[e];
}

// ---------------- mean aggregation (fp16 in/out), all types, warp per dst row ----------------
__global__ void k_aggregate_all() {
    int w = (blockIdx.x * blockDim.x + threadIdx.x) >> 5;
    int lane = threadIdx.x & 31;
    if (w >= TOTDST) return;
    // src table offset by global dst row range
    size_t srcoff = (w < 300000) ? 0 : (w < 500000) ? (size_t)NA : (size_t)(NA + NE);
    const uint32_t* xs = g_xh32 + srcoff * 64;
    int start = g_rowstart[w];
    int c = g_cnt[w];
    float4 acc = make_float4(0.f, 0.f, 0.f, 0.f);
    for (int j = 0; j < c; j++) {
        int s = __ldg(&g_edge_src[start + j]);
        uint2 v = __ldg((const uint2*)(xs + (size_t)s * 64) + lane);
        __half2 h0 = *(__half2*)&v.x;
        __half2 h1 = *(__half2*)&v.y;
        float2 f0 = __half22float2(h0);
        float2 f1 = __half22float2(h1);
        acc.x += f0.x; acc.y += f0.y; acc.z += f1.x; acc.w += f1.y;
    }
    float inv = 1.0f / (float)(c > 1 ? c : 1);
    __half2 o0 = __floats2half2_rn(acc.x * inv, acc.y * inv);
    __half2 o1 = __floats2half2_rn(acc.z * inv, acc.w * inv);
    uint2 ov;
    ov.x = *(uint32_t*)&o0;
    ov.y = *(uint32_t*)&o1;
    *((uint2*)(g_agg32 + (size_t)w * 64) + lane) = ov;
}

// ---------------- fp16 tensor-core fused GEMM ----------------
// out[m][n] = normalize( [x_dst|agg][m][0:256] @ [wl|wr][n][0:256]^T + b[n] )
// mma.m16n8k16: A = W tile (n-major), B = X tile (m-major). K streamed in 16 stages of k16.

#define SROW 12   // smem row stride in uint32 words (8 data + 4 pad): 12g+tg distinct mod 32

__global__ __launch_bounds__(256, 2)
void k_sage_gemm_f16(const __half* __restrict__ xdh,   // dst-type fp16 features
                     const __half* __restrict__ aggh,  // this type's agg section
                     const __half* __restrict__ wlh,   // wl halves; wr = wlh + 16384
                     const float* __restrict__ bias,
                     float* __restrict__ out, int n_dst, int accumulate)
{
    __shared__ uint32_t sX[2][128 * SROW];
    __shared__ uint32_t sW[2][128 * SROW];
    __shared__ float sSS[128];

    const int tid = threadIdx.x;
    const int lane = tid & 31;
    const int warpId = tid >> 5;
    const int warpN = warpId & 1;       // 2 tiles of 64 n
    const int warpM = warpId >> 1;      // 4 tiles of 32 m
    const int g = lane >> 2;            // 0..7
    const int tg = lane & 3;            // 0..3
    const int m0 = blockIdx.x * 128;

    // loader: threads 0..127 own X rows, 128..255 own W rows; 32B (one k16 row-chunk) per stage
    const int lr = tid & 127;
    const bool isW = tid >= 128;
    const __half* wrh = wlh + 16384;

    float c[4][4][4];
#pragma unroll
    for (int a = 0; a < 4; a++)
#pragma unroll
        for (int b = 0; b < 4; b++)
#pragma unroll
            for (int r = 0; r < 4; r++) c[a][b][r] = 0.f;

    uint4 st0;

    auto load_regs = [&](int kt) {
        int kb = (kt & 7) * 32;   // byte offset within 256B half-row
        if (!isW) {
            int m = m0 + lr;
            if (m < n_dst) {
                const char* src = (const char*)((kt < 8) ? xdh : aggh) + (size_t)m * 256 + kb;
                st0 = *(const uint4*)src;
                // second 16B loaded below via st1 path merged: use two uint4s
            } else {
                st0 = make_uint4(0, 0, 0, 0);
            }
        } else {
            const char* src = (const char*)((kt < 8) ? wlh : wrh) + (size_t)lr * 256 + kb;
            st0 = *(const uint4*)src;
        }
    };
    // we need 32B per stage: handle as two uint4s
    uint4 st1;
    auto load_regs2 = [&](int kt) {
        int kb = (kt & 7) * 32 + 16;
        if (!isW) {
            int m = m0 + lr;
            if (m < n_dst) {
                const char* src = (const char*)((kt < 8) ? xdh : aggh) + (size_t)m * 256 + kb;
                st1 = *(const uint4*)src;
            } else {
                st1 = make_uint4(0, 0, 0, 0);
            }
        } else {
            const char* src = (const char*)((kt < 8) ? wlh : wrh) + (size_t)lr * 256 + kb;
            st1 = *(const uint4*)src;
        }
    };

    auto store_tile = [&](int buf) {
        uint32_t* s = (isW ? sW[buf] : sX[buf]) + lr * SROW;
        *(uint4*)s = st0;
        *(uint4*)(s + 4) = st1;
    };

    load_regs(0);
    load_regs2(0);
    store_tile(0);
    __syncthreads();

    for (int kt = 0; kt < 16; kt++) {
        int cur = kt & 1;
        if (kt < 15) { load_regs(kt + 1); load_regs2(kt + 1); }

        const uint32_t* sXc = sX[cur];
        const uint32_t* sWc = sW[cur];

        // B fragments (X tile): per mt, b0 = word tg, b1 = word tg+4 of row (warpM*32+mt*8+g)
        uint32_t Bf[4][2];
#pragma unroll
        for (int mt = 0; mt < 4; mt++) {
            int base = (warpM * 32 + mt * 8 + g) * SROW + tg;
            Bf[mt][0] = sXc[base];
            Bf[mt][1] = sXc[base + 4];
        }
#pragma unroll
        for (int nt = 0; nt < 4; nt++) {
            int rw = (warpN * 64 + nt * 16 + g) * SROW + tg;
            uint32_t a0 = sWc[rw];
            uint32_t a1 = sWc[rw + 8 * SROW];
            uint32_t a2 = sWc[rw + 4];
            uint32_t a3 = sWc[rw + 8 * SROW + 4];
#pragma unroll
            for (int mt = 0; mt < 4; mt++) {
                asm volatile(
                    "mma.sync.aligned.m16n8k16.row.col.f32.f16.f16.f32 "
                    "{%0,%1,%2,%3}, {%4,%5,%6,%7}, {%8,%9}, {%0,%1,%2,%3};\n"
                    : "+f"(c[nt][mt][0]), "+f"(c[nt][mt][1]),
                      "+f"(c[nt][mt][2]), "+f"(c[nt][mt][3])
                    : "r"(a0), "r"(a1), "r"(a2), "r"(a3),
                      "r"(Bf[mt][0]), "r"(Bf[mt][1]));
            }
        }

        if (kt < 15) {
            __syncthreads();
            store_tile(cur ^ 1);
            __syncthreads();
        }
    }

    // ---------------- epilogue: bias, per-row L2 norm, (accumulate,) store ----------------
    // lane holds out[n][m]: n = warpN*64 + nt*16 + g + (r>>1)*8, m_local = warpM*32 + mt*8 + 2tg + (r&1)
    float bias_v[4][2];
#pragma unroll
    for (int nt = 0; nt < 4; nt++) {
        int n = warpN * 64 + nt * 16 + g;
        bias_v[nt][0] = __ldg(&bias[n]);
        bias_v[nt][1] = __ldg(&bias[n + 8]);
    }
#pragma unroll
    for (int nt = 0; nt < 4; nt++)
#pragma unroll
        for (int mt = 0; mt < 4; mt++)
#pragma unroll
            for (int r = 0; r < 4; r++)
                c[nt][mt][r] += bias_v[nt][r >> 1];

    __syncthreads();
    if (tid < 128) sSS[tid] = 0.f;
    __syncthreads();

    float ps[4][2];
#pragma unroll
    for (int mt = 0; mt < 4; mt++)
#pragma unroll
        for (int j = 0; j < 2; j++) {
            float s = 0.f;
#pragma unroll
            for (int nt = 0; nt < 4; nt++) {
                float v0 = c[nt][mt][j];
                float v1 = c[nt][mt][2 + j];
                s += v0 * v0 + v1 * v1;
            }
            s += __shfl_xor_sync(0xFFFFFFFFu, s, 4);
            s += __shfl_xor_sync(0xFFFFFFFFu, s, 8);
            s += __shfl_xor_sync(0xFFFFFFFFu, s, 16);
            ps[mt][j] = s;
        }
    if (g == 0) {
#pragma unroll
        for (int mt = 0; mt < 4; mt++)
#pragma unroll
            for (int j = 0; j < 2; j++)
                atomicAdd(&sSS[warpM * 32 + mt * 8 + 2 * tg + j], ps[mt][j]);
    }
    __syncthreads();

#pragma unroll
    for (int mt = 0; mt < 4; mt++) {
#pragma unroll
        for (int j = 0; j < 2; j++) {
            int mloc = warpM * 32 + mt * 8 + 2 * tg + j;
            int m = m0 + mloc;
            if (m >= n_dst) continue;
            float nrm = sqrtf(sSS[mloc]);
            float scale = 1.0f / fmaxf(nrm, 1e-12f);
            float* orow = out + (size_t)m * DD;
#pragma unroll
            for (int nt = 0; nt < 4; nt++) {
#pragma unroll
                for (int h = 0; h < 2; h++) {
                    int n = warpN * 64 + nt * 16 + g + h * 8;
                    float v = c[nt][mt][2 * h + j] * scale;
                    if (accumulate) v += orow[n];
                    orow[n] = v;
                }
            }
        }
    }
}

extern "C" void kernel_launch(void* const* d_in, const int* in_sizes, int n_in,
                              void* d_out, int out_size)
{
    const float* xa = (const float*)d_in[0];
    const float* xe = (const float*)d_in[1];
    const float* xf = (const float*)d_in[2];

    const int* si[5];
    const int* di[5];
    for (int t = 0; t < 5; t++) {
        si[t] = (const int*)d_in[3 + 2 * t];
        di[t] = (const int*)d_in[4 + 2 * t];
    }
    const float* wl[5];
    const float* bb[5];
    const float* wr[5];
    for (int t = 0; t < 5; t++) {
        wl[t] = (const float*)d_in[13 + 3 * t];
        bb[t] = (const float*)d_in[14 + 3 * t];
        wr[t] = (const float*)d_in[15 + 3 * t];
    }

    float* out = (float*)d_out;
    float* out_article = out;
    float* out_entity  = out + (size_t)NA * DD;
    float* out_fact    = out + (size_t)(NA + NE) * DD;

    // ---- pre-pass: fp32 -> fp16 copies ----
    {
        dim3 gx((NE * 32 + 255) / 256, 3);   // max section (NE) covers all; guard inside
        k_tohalf_x<<<gx, 256>>>(xa, xe, xf);
        dim3 gw(16, 10);
        k_tohalf_w<<<gw, 256>>>(wl[0], wr[0], wl[1], wr[1], wl[2], wr[2], wl[3], wr[3], wl[4], wr[4]);
    }

    // ---- batched CSR build ----
    k_zero_cnt<<<(TOTDST + 255) / 256, 256>>>();
    {
        dim3 gh((NEDGE + 255) / 256, 5);
        k_hist<<<gh, 256>>>(di[0], di[1], di[2], di[3], di[4]);
    }
    int nb = (TOTDST + 4095) / 4096;
    k_scan1<<<nb, 1024>>>();
    k_scan2<<<1, 256>>>(nb);
    k_scan3<<<(TOTDST + 255) / 256, 256>>>();
    {
        dim3 gh((NEDGE + 255) / 256, 5);
        k_scatter<<<gh, 256>>>(si[0], si[1], si[2], si[3], si[4],
                               di[0], di[1], di[2], di[3], di[4]);
    }

    // ---- aggregation (all types) ----
    k_aggregate_all<<<(TOTDST * 32 + 255) / 256, 256>>>();

    // ---- GEMMs ----
    // dst x-table offsets (rows): entity=NA, fact=NA+NE, article=0
    const size_t xoff[5]  = {(size_t)NA, (size_t)(NA + NE), 0, (size_t)(NA + NE), (size_t)NA};
    const size_t aoff[5]  = {0, 200000, 300000, 400000, 500000};
    const int    ndst[5]  = {NE, NF, NA, NF, NE};
    float* osec[5]        = {out_entity, out_fact, out_article, out_fact, out_entity};
    const int    acc[5]   = {0, 0, 0, 1, 1};

    for (int t = 0; t < 5; t++) {
        const __half* xdh  = (const __half*)g_xh32  ? (const __half*)nullptr : nullptr; // placeholder (replaced below)
        (void)xdh;
    }

    for (int t = 0; t < 5; t++) {
        __half* xh_base;  cudaGetSymbolAddress((void**)&xh_base,  g_xh32);
        __half* ag_base;  cudaGetSymbolAddress((void**)&ag_base,  g_agg32);
        __half* wh_base;  cudaGetSymbolAddress((void**)&wh_base,  g_wh32);
        const __half* xdh = xh_base + xoff[t] * DD;
        const __half* agh = ag_base + aoff[t] * DD;
        const __half* wlh = wh_base + (size_t)t * 2 * 16384;
        k_sage_gemm_f16<<<(ndst[t] + 127) / 128, 256>>>(xdh, agh, wlh, bb[t], osec[t], ndst[t], acc[t]);
    }
}

// round 6
// speedup vs baseline: 2.3566x; 1.0297x over previous
#include <cuda_runtime.h>
#include <cuda_fp16.h>
#include <cstdint>

#define NA 100000
#define NE 200000
#define NF 100000
#define DD 128
#define NEDGE 400000
#define TOTDST 700000
#define TOTEDGE 2000000
#define TOTSRC 400000   // xa + xe + xf rows

// ---------------- scratch (device globals: allocation-free) ----------------
__device__ uint32_t g_xh32[(size_t)TOTSRC * 64];   // 102.4 MB  [xa|xe|xf] rows x 128 halves
__device__ uint32_t g_wh32[5 * 2 * 8192];          // 5 types x {wl,wr} x 128x128 halves
__device__ int   g_cnt[TOTDST];
__device__ int   g_rowstart[TOTDST];
__device__ int   g_cursor[TOTDST];
__device__ int   g_edge_src[TOTEDGE];
__device__ int   g_bsums[256];

// ---------------- fp32 -> fp16 pre-pass ----------------
__global__ void k_tohalf_x(const float* __restrict__ xa, const float* __restrict__ xe,
                           const float* __restrict__ xf) {
    int y = blockIdx.y;
    const float* src = (y == 0) ? xa : (y == 1) ? xe : xf;
    int rows = (y == 1) ? NE : NA;
    size_t dstoff = (y == 0) ? 0 : (y == 1) ? (size_t)NA * 32 : (size_t)(NA + NE) * 32;
    int n4 = rows * 32;
    int i = blockIdx.x * 256 + threadIdx.x;
    if (i >= n4) return;
    float4 v = ((const float4*)src)[i];
    __half2 a = __floats2half2_rn(v.x, v.y);
    __half2 b = __floats2half2_rn(v.z, v.w);
    uint32_t* d = g_xh32 + dstoff * 2 + (size_t)i * 2;
    d[0] = *(uint32_t*)&a;
    d[1] = *(uint32_t*)&b;
}

__global__ void k_tohalf_w(const float* p0, const float* p1, const float* p2, const float* p3,
                           const float* p4, const float* p5, const float* p6, const float* p7,
                           const float* p8, const float* p9) {
    int y = blockIdx.y;
    const float* src = (y == 0) ? p0 : (y == 1) ? p1 : (y == 2) ? p2 : (y == 3) ? p3 :
                       (y == 4) ? p4 : (y == 5) ? p5 : (y == 6) ? p6 : (y == 7) ? p7 :
                       (y == 8) ? p8 : p9;
    int i = blockIdx.x * 256 + threadIdx.x;
    if (i >= 4096) return;
    float4 v = ((const float4*)src)[i];
    __half2 a = __floats2half2_rn(v.x, v.y);
    __half2 b = __floats2half2_rn(v.z, v.w);
    uint32_t* d = g_wh32 + (size_t)y * 8192 + (size_t)i * 2;
    d[0] = *(uint32_t*)&a;
    d[1] = *(uint32_t*)&b;
}

// ---------------- batched CSR build ----------------
__global__ void k_zero_cnt() {
    int i = blockIdx.x * blockDim.x + threadIdx.x;
    if (i < TOTDST) g_cnt[i] = 0;
}

__device__ __forceinline__ int dst_off_of(int t) {
    return (t == 0) ? 0 : (t == 1) ? 200000 : (t == 2) ? 300000 : (t == 3) ? 400000 : 500000;
}

__global__ void k_hist(const int* d0, const int* d1, const int* d2, const int* d3, const int* d4) {
    int e = blockIdx.x * 256 + threadIdx.x;
    if (e >= NEDGE) return;
    int t = blockIdx.y;
    const int* di = (t == 0) ? d0 : (t == 1) ? d1 : (t == 2) ? d2 : (t == 3) ? d3 : d4;
    atomicAdd(&g_cnt[dst_off_of(t) + di[e]], 1);
}

__global__ void k_scan1() {
    __shared__ int s[1024];
    int t = threadIdx.x;
    int base = blockIdx.x * 4096;
    int v[4];
    int sum = 0;
#pragma unroll
    for (int j = 0; j < 4; j++) {
        int idx = base + t * 4 + j;
        v[j] = (idx < TOTDST) ? g_cnt[idx] : 0;
        sum += v[j];
    }
    s[t] = sum;
    __syncthreads();
    for (int off = 1; off < 1024; off <<= 1) {
        int x = (t >= off) ? s[t - off] : 0;
        __syncthreads();
        if (t >= off) s[t] += x;
        __syncthreads();
    }
    int excl = s[t] - sum;
    if (t == 1023) g_bsums[blockIdx.x] = s[1023];
    int run = excl;
#pragma unroll
    for (int j = 0; j < 4; j++) {
        int idx = base + t * 4 + j;
        if (idx < TOTDST) g_rowstart[idx] = run;
        run += v[j];
    }
}

__global__ void k_scan2(int nb) {
    __shared__ int s[256];
    int t = threadIdx.x;
    int v = (t < nb) ? g_bsums[t] : 0;
    s[t] = v;
    __syncthreads();
    for (int off = 1; off < 256; off <<= 1) {
        int x = (t >= off) ? s[t - off] : 0;
        __syncthreads();
        s[t] += x;
        __syncthreads();
    }
    if (t < nb) g_bsums[t] = s[t] - v;
}

__global__ void k_scan3() {
    int i = blockIdx.x * blockDim.x + threadIdx.x;
    if (i < TOTDST) {
        int r = g_rowstart[i] + g_bsums[i >> 12];
        g_rowstart[i] = r;
        g_cursor[i] = r;
    }
}

__global__ void k_scatter(const int* s0, const int* s1, const int* s2, const int* s3, const int* s4,
                          const int* d0, const int* d1, const int* d2, const int* d3, const int* d4) {
    int e = blockIdx.x * 256 + threadIdx.x;
    if (e >= NEDGE) return;
    int t = blockIdx.y;
    const int* si = (t == 0) ? s0 : (t == 1) ? s1 : (t == 2) ? s2 : (t == 3) ? s3 : s4;
    const int* di = (t == 0) ? d0 : (t == 1) ? d1 : (t == 2) ? d2 : (t == 3) ? d3 : d4;
    int d = dst_off_of(t) + di[e];
    int p = atomicAdd(&g_cursor[d], 1);
    g_edge_src[p] = si[e];
}

// ---------------- fused aggregate + dual-type GEMM + normalize + combine ----------------
// Blocks grouped by destination node kind. Per type: aggregate 128 dst rows into smem
// (fp16, stride 68 words -> conflict-free in-place MMA B-fragment reads), then
// GEMM over K=256 = [x_dst | agg] @ [wl | wr]^T, bias, L2-normalize, store/RMW.

#define SROW 12      // staged-tile row stride (words)
#define AROW 68      // agg tile row stride (words); 68 mod 32 == 4 -> conflict-free frags
#define AB 782       // ceil(NA/128)
#define EB 1563      // ceil(NE/128)

__global__ __launch_bounds__(256, 2)
void k_fused(const float* __restrict__ b0, const float* __restrict__ b1,
             const float* __restrict__ b2, const float* __restrict__ b3,
             const float* __restrict__ b4, float* __restrict__ out)
{
    extern __shared__ uint32_t dyn[];
    uint32_t* sW   = dyn;              // 2 x 128 x 12 = 3072 words
    uint32_t* sX   = dyn + 3072;       // 2 x 128 x 12 = 3072 words
    uint32_t* sAgg = dyn + 6144;       // 128 x 68 = 8704 words
    float*    sSS  = (float*)(dyn + 14848);  // 128 words

    const int tid = threadIdx.x;
    const int lane = tid & 31;
    const int warpId = tid >> 5;
    const int warpN = warpId & 1;
    const int warpM = warpId >> 1;
    const int g = lane >> 2;
    const int tg = lane & 3;

    int b = blockIdx.x;
    int kind, mblk;
    if (b < AB) { kind = 0; mblk = b; }
    else if (b < AB + EB) { kind = 1; mblk = b - AB; }
    else { kind = 2; mblk = b - (AB + EB); }
    const int m0 = mblk * 128;
    const int ndst = (kind == 1) ? NE : NA;
    const size_t xRowOff = (kind == 0) ? 0 : (kind == 1) ? (size_t)NA : (size_t)(NA + NE);
    float* osec = out + ((kind == 0) ? 0 : (kind == 1) ? (size_t)NA * DD : (size_t)(NA + NE) * DD);
    const int tA = (kind == 0) ? 2 : (kind == 1) ? 0 : 1;
    const int tB = (kind == 0) ? -1 : (kind == 1) ? 4 : 3;
    const int ntypes = (kind == 0) ? 1 : 2;

    const int lr = tid & 127;
    const bool isW = tid >= 128;

    for (int it = 0; it < ntypes; it++) {
        const int t = (it == 0) ? tA : tB;
        const int dOff = dst_off_of(t);
        const size_t sOff = (t <= 1) ? 0 : (t <= 3) ? (size_t)NA : (size_t)(NA + NE);
        const uint32_t* wbase = g_wh32 + (size_t)t * 16384;
        const float* bias = (t == 0) ? b0 : (t == 1) ? b1 : (t == 2) ? b2 : (t == 3) ? b3 : b4;

        __syncthreads();   // prior iteration done with sAgg / sSS

        // ---- phase A: mean-aggregate 128 rows into sAgg (2 rows in flight per warp) ----
        {
            int half = lane >> 4;
            int l16 = lane & 15;
            for (int rr = warpId * 2 + half; rr < 128; rr += 16) {
                int m = m0 + rr;
                float f[8] = {0.f, 0.f, 0.f, 0.f, 0.f, 0.f, 0.f, 0.f};
                int cnt = 0;
                if (m < ndst) {
                    int gid = dOff + m;
                    int start = __ldg(&g_rowstart[gid]);
                    cnt = __ldg(&g_cnt[gid]);
                    for (int j = 0; j < cnt; j++) {
                        int s = __ldg(&g_edge_src[start + j]);
                        uint4 v = __ldg((const uint4*)(g_xh32 + ((size_t)(sOff + s)) * 64 + l16 * 4));
                        __half2 h; float2 q;
                        h = *(__half2*)&v.x; q = __half22float2(h); f[0] += q.x; f[1] += q.y;
                        h = *(__half2*)&v.y; q = __half22float2(h); f[2] += q.x; f[3] += q.y;
                        h = *(__half2*)&v.z; q = __half22float2(h); f[4] += q.x; f[5] += q.y;
                        h = *(__half2*)&v.w; q = __half22float2(h); f[6] += q.x; f[7] += q.y;
                    }
                }
                float inv = 1.0f / (float)(cnt > 1 ? cnt : 1);
                uint4 o;
                __half2 h0 = __floats2half2_rn(f[0] * inv, f[1] * inv); o.x = *(uint32_t*)&h0;
                __half2 h1 = __floats2half2_rn(f[2] * inv, f[3] * inv); o.y = *(uint32_t*)&h1;
                __half2 h2 = __floats2half2_rn(f[4] * inv, f[5] * inv); o.z = *(uint32_t*)&h2;
                __half2 h3 = __floats2half2_rn(f[6] * inv, f[7] * inv); o.w = *(uint32_t*)&h3;
                *(uint4*)(sAgg + rr * AROW + l16 * 4) = o;
            }
        }
        if (tid < 128) sSS[tid] = 0.f;
        __syncthreads();

        // ---- phase B: K=256 mainloop ----
        float c[4][4][4];
#pragma unroll
        for (int a = 0; a < 4; a++)
#pragma unroll
            for (int bb2 = 0; bb2 < 4; bb2++)
#pragma unroll
                for (int r = 0; r < 4; r++) c[a][bb2][r] = 0.f;

        uint4 st0, st1;
        auto load_stage = [&](int kt) {
            if (!isW) {
                if (kt < 8) {
                    int m = m0 + lr;
                    if (m < ndst) {
                        const uint32_t* src = g_xh32 + ((size_t)(xRowOff + m)) * 64 + kt * 8;
                        st0 = *(const uint4*)src;
                        st1 = *(const uint4*)(src + 4);
                    } else {
                        st0 = make_uint4(0, 0, 0, 0);
                        st1 = st0;
                    }
                }
            } else {
                const uint32_t* src = wbase + ((kt >= 8) ? 8192 : 0) + lr * 64 + (kt & 7) * 8;
                st0 = *(const uint4*)src;
                st1 = *(const uint4*)(src + 4);
            }
        };
        auto store_stage = [&](int buf, int kt) {
            if (!isW) {
                if (kt < 8) {
                    uint32_t* s = sX + buf * 1536 + lr * SROW;
                    *(uint4*)s = st0;
                    *(uint4*)(s + 4) = st1;
                }
            } else {
                uint32_t* s = sW + buf * 1536 + lr * SROW;
                *(uint4*)s = st0;
                *(uint4*)(s + 4) = st1;
            }
        };

        load_stage(0);
        store_stage(0, 0);
        __syncthreads();

        for (int kt = 0; kt < 16; kt++) {
            int cur = kt & 1;
            if (kt < 15) load_stage(kt + 1);

            const uint32_t* sWc = sW + cur * 1536;
            uint32_t Bf[4][2];
            if (kt < 8) {
                const uint32_t* sXc = sX + cur * 1536;
#pragma unroll
                for (int mt = 0; mt < 4; mt++) {
                    int base = (warpM * 32 + mt * 8 + g) * SROW + tg;
                    Bf[mt][0] = sXc[base];
                    Bf[mt][1] = sXc[base + 4];
                }
            } else {
#pragma unroll
                for (int mt = 0; mt < 4; mt++) {
                    int base = (warpM * 32 + mt * 8 + g) * AROW + (kt - 8) * 8 + tg;
                    Bf[mt][0] = sAgg[base];
                    Bf[mt][1] = sAgg[base + 4];
                }
            }
#pragma unroll
            for (int nt = 0; nt < 4; nt++) {
                int rw = (warpN * 64 + nt * 16 + g) * SROW + tg;
                uint32_t a0 = sWc[rw];
                uint32_t a1 = sWc[rw + 8 * SROW];
                uint32_t a2 = sWc[rw + 4];
                uint32_t a3 = sWc[rw + 8 * SROW + 4];
#pragma unroll
                for (int mt = 0; mt < 4; mt++) {
                    asm volatile(
                        "mma.sync.aligned.m16n8k16.row.col.f32.f16.f16.f32 "
                        "{%0,%1,%2,%3}, {%4,%5,%6,%7}, {%8,%9}, {%0,%1,%2,%3};\n"
                        : "+f"(c[nt][mt][0]), "+f"(c[nt][mt][1]),
                          "+f"(c[nt][mt][2]), "+f"(c[nt][mt][3])
                        : "r"(a0), "r"(a1), "r"(a2), "r"(a3),
                          "r"(Bf[mt][0]), "r"(Bf[mt][1]));
                }
            }

            if (kt < 15) {
                store_stage(cur ^ 1, kt + 1);
                __syncthreads();
            }
        }

        // ---- epilogue: bias, per-row L2 norm, store (it==0) or RMW add (it==1) ----
        float bias_v[4][2];
#pragma unroll
        for (int nt = 0; nt < 4; nt++) {
            int n = warpN * 64 + nt * 16 + g;
            bias_v[nt][0] = __ldg(&bias[n]);
            bias_v[nt][1] = __ldg(&bias[n + 8]);
        }
#pragma unroll
        for (int nt = 0; nt < 4; nt++)
#pragma unroll
            for (int mt = 0; mt < 4; mt++)
#pragma unroll
                for (int r = 0; r < 4; r++)
                    c[nt][mt][r] += bias_v[nt][r >> 1];

        float ps[4][2];
#pragma unroll
        for (int mt = 0; mt < 4; mt++)
#pragma unroll
            for (int j = 0; j < 2; j++) {
                float s = 0.f;
#pragma unroll
                for (int nt = 0; nt < 4; nt++) {
                    float v0 = c[nt][mt][j];
                    float v1 = c[nt][mt][2 + j];
                    s += v0 * v0 + v1 * v1;
                }
                s += __shfl_xor_sync(0xFFFFFFFFu, s, 4);
                s += __shfl_xor_sync(0xFFFFFFFFu, s, 8);
                s += __shfl_xor_sync(0xFFFFFFFFu, s, 16);
                ps[mt][j] = s;
            }
        if (g == 0) {
#pragma unroll
            for (int mt = 0; mt < 4; mt++)
#pragma unroll
                for (int j = 0; j < 2; j++)
                    atomicAdd(&sSS[warpM * 32 + mt * 8 + 2 * tg + j], ps[mt][j]);
        }
        __syncthreads();

#pragma unroll
        for (int mt = 0; mt < 4; mt++) {
#pragma unroll
            for (int j = 0; j < 2; j++) {
                int mloc = warpM * 32 + mt * 8 + 2 * tg + j;
                int m = m0 + mloc;
                if (m >= ndst) continue;
                float nrm = sqrtf(sSS[mloc]);
                float scale = 1.0f / fmaxf(nrm, 1e-12f);
                float* orow = osec + (size_t)m * DD;
#pragma unroll
                for (int nt = 0; nt < 4; nt++) {
#pragma unroll
                    for (int h = 0; h < 2; h++) {
                        int n = warpN * 64 + nt * 16 + g + h * 8;
                        float v = c[nt][mt][2 * h + j] * scale;
                        if (it > 0) v += orow[n];
                        orow[n] = v;
                    }
                }
            }
        }
    }
}

extern "C" void kernel_launch(void* const* d_in, const int* in_sizes, int n_in,
                              void* d_out, int out_size)
{
    const float* xa = (const float*)d_in[0];
    const float* xe = (const float*)d_in[1];
    const float* xf = (const float*)d_in[2];

    const int* si[5];
    const int* di[5];
    for (int t = 0; t < 5; t++) {
        si[t] = (const int*)d_in[3 + 2 * t];
        di[t] = (const int*)d_in[4 + 2 * t];
    }
    const float* wl[5];
    const float* bb[5];
    const float* wr[5];
    for (int t = 0; t < 5; t++) {
        wl[t] = (const float*)d_in[13 + 3 * t];
        bb[t] = (const float*)d_in[14 + 3 * t];
        wr[t] = (const float*)d_in[15 + 3 * t];
    }

    float* out = (float*)d_out;

    // ---- pre-pass: fp32 -> fp16 copies ----
    {
        dim3 gx((NE * 32 + 255) / 256, 3);
        k_tohalf_x<<<gx, 256>>>(xa, xe, xf);
        dim3 gw(16, 10);
        k_tohalf_w<<<gw, 256>>>(wl[0], wr[0], wl[1], wr[1], wl[2], wr[2], wl[3], wr[3], wl[4], wr[4]);
    }

    // ---- batched CSR build ----
    k_zero_cnt<<<(TOTDST + 255) / 256, 256>>>();
    {
        dim3 gh((NEDGE + 255) / 256, 5);
        k_hist<<<gh, 256>>>(di[0], di[1], di[2], di[3], di[4]);
    }
    int nb = (TOTDST + 4095) / 4096;
    k_scan1<<<nb, 1024>>>();
    k_scan2<<<1, 256>>>(nb);
    k_scan3<<<(TOTDST + 255) / 256, 256>>>();
    {
        dim3 gh((NEDGE + 255) / 256, 5);
        k_scatter<<<gh, 256>>>(si[0], si[1], si[2], si[3], si[4],
                               di[0], di[1], di[2], di[3], di[4]);
    }

    // ---- fused aggregate + GEMM + normalize + combine (single launch) ----
    const int SMEM_BYTES = (14848 + 128) * 4;   // 59,904 B
    cudaFuncSetAttribute(k_fused, cudaFuncAttributeMaxDynamicSharedMemorySize, SMEM_BYTES);
    k_fused<<<AB + EB + AB, 256, SMEM_BYTES>>>(bb[0], bb[1], bb[2], bb[3], bb[4], out);
}

// round 8
// speedup vs baseline: 2.5851x; 1.0970x over previous
#include <cuda_runtime.h>
#include <cuda_fp16.h>
#include <cstdint>

#define NA 100000
#define NE 200000
#define NF 100000
#define DD 128
#define NEDGE 400000
#define TOTDST 700000
#define TOTEDGE 2000000
#define TOTSRC 400000   // xa + xe + xf rows

// ---------------- scratch (device globals: allocation-free) ----------------
__device__ uint32_t g_xh32[(size_t)TOTSRC * 64];   // 102.4 MB  [xa|xe|xf] rows x 128 halves
__device__ uint32_t g_wh32[5 * 2 * 8192];          // 5 types x {wl,wr} x 128x128 halves
__device__ int   g_cnt[TOTDST];
__device__ int   g_rowstart[TOTDST];
__device__ int   g_cursor[TOTDST];
__device__ int   g_edge_src[TOTEDGE];
__device__ int   g_bsums[256];

// ---------------- fp32 -> fp16 pre-pass ----------------
__global__ void k_tohalf_x(const float* __restrict__ xa, const float* __restrict__ xe,
                           const float* __restrict__ xf) {
    int y = blockIdx.y;
    const float* src = (y == 0) ? xa : (y == 1) ? xe : xf;
    int rows = (y == 1) ? NE : NA;
    size_t dstoff = (y == 0) ? 0 : (y == 1) ? (size_t)NA * 32 : (size_t)(NA + NE) * 32;
    int n4 = rows * 32;
    int i = blockIdx.x * 256 + threadIdx.x;
    if (i >= n4) return;
    float4 v = ((const float4*)src)[i];
    __half2 a = __floats2half2_rn(v.x, v.y);
    __half2 b = __floats2half2_rn(v.z, v.w);
    uint32_t* d = g_xh32 + dstoff * 2 + (size_t)i * 2;
    d[0] = *(uint32_t*)&a;
    d[1] = *(uint32_t*)&b;
}

__global__ void k_tohalf_w(const float* p0, const float* p1, const float* p2, const float* p3,
                           const float* p4, const float* p5, const float* p6, const float* p7,
                           const float* p8, const float* p9) {
    int y = blockIdx.y;
    const float* src = (y == 0) ? p0 : (y == 1) ? p1 : (y == 2) ? p2 : (y == 3) ? p3 :
                       (y == 4) ? p4 : (y == 5) ? p5 : (y == 6) ? p6 : (y == 7) ? p7 :
                       (y == 8) ? p8 : p9;
    int i = blockIdx.x * 256 + threadIdx.x;
    if (i >= 4096) return;
    float4 v = ((const float4*)src)[i];
    __half2 a = __floats2half2_rn(v.x, v.y);
    __half2 b = __floats2half2_rn(v.z, v.w);
    uint32_t* d = g_wh32 + (size_t)y * 8192 + (size_t)i * 2;
    d[0] = *(uint32_t*)&a;
    d[1] = *(uint32_t*)&b;
}

// ---------------- batched CSR build ----------------
__global__ void k_zero_cnt() {
    int i = blockIdx.x * blockDim.x + threadIdx.x;
    if (i < TOTDST) g_cnt[i] = 0;
}

__device__ __forceinline__ int dst_off_of(int t) {
    return (t == 0) ? 0 : (t == 1) ? 200000 : (t == 2) ? 300000 : (t == 3) ? 400000 : 500000;
}

__global__ void k_hist(const int* d0, const int* d1, const int* d2, const int* d3, const int* d4) {
    int e = blockIdx.x * 256 + threadIdx.x;
    if (e >= NEDGE) return;
    int t = blockIdx.y;
    const int* di = (t == 0) ? d0 : (t == 1) ? d1 : (t == 2) ? d2 : (t == 3) ? d3 : d4;
    atomicAdd(&g_cnt[dst_off_of(t) + di[e]], 1);
}

__global__ void k_scan1() {
    __shared__ int s[1024];
    int t = threadIdx.x;
    int base = blockIdx.x * 4096;
    int v[4];
    int sum = 0;
#pragma unroll
    for (int j = 0; j < 4; j++) {
        int idx = base + t * 4 + j;
        v[j] = (idx < TOTDST) ? g_cnt[idx] : 0;
        sum += v[j];
    }
    s[t] = sum;
    __syncthreads();
    for (int off = 1; off < 1024; off <<= 1) {
        int x = (t >= off) ? s[t - off] : 0;
        __syncthreads();
        if (t >= off) s[t] += x;
        __syncthreads();
    }
    int excl = s[t] - sum;
    if (t == 1023) g_bsums[blockIdx.x] = s[1023];
    int run = excl;
#pragma unroll
    for (int j = 0; j < 4; j++) {
        int idx = base + t * 4 + j;
        if (idx < TOTDST) g_rowstart[idx] = run;
        run += v[j];
    }
}

__global__ void k_scan2(int nb) {
    __shared__ int s[256];
    int t = threadIdx.x;
    int v = (t < nb) ? g_bsums[t] : 0;
    s[t] = v;
    __syncthreads();
    for (int off = 1; off < 256; off <<= 1) {
        int x = (t >= off) ? s[t - off] : 0;
        __syncthreads();
        s[t] += x;
        __syncthreads();
    }
    if (t < nb) g_bsums[t] = s[t] - v;
}

__global__ void k_scan3() {
    int i = blockIdx.x * blockDim.x + threadIdx.x;
    if (i < TOTDST) {
        int r = g_rowstart[i] + g_bsums[i >> 12];
        g_rowstart[i] = r;
        g_cursor[i] = r;
    }
}

__global__ void k_scatter(const int* s0, const int* s1, const int* s2, const int* s3, const int* s4,
                          const int* d0, const int* d1, const int* d2, const int* d3, const int* d4) {
    int e = blockIdx.x * 256 + threadIdx.x;
    if (e >= NEDGE) return;
    int t = blockIdx.y;
    const int* si = (t == 0) ? s0 : (t == 1) ? s1 : (t == 2) ? s2 : (t == 3) ? s3 : s4;
    const int* di = (t == 0) ? d0 : (t == 1) ? d1 : (t == 2) ? d2 : (t == 3) ? d3 : d4;
    int d = dst_off_of(t) + di[e];
    int p = atomicAdd(&g_cursor[d], 1);
    g_edge_src[p] = si[e];
}

// ---------------- fused aggregate + dual-type GEMM + normalize + combine ----------------
// Phase A aggregates BOTH edge types' 128 dst rows (256 rows) with edge-batched
// (unroll-4) gathers for MLP; phase B runs the two K=256 GEMMs back-to-back.

#define SROW 12      // staged-tile row stride (words)
#define AROW 68      // agg tile row stride (words); 68 mod 32 == 4 -> conflict-free frags
#define AGGW 8704    // words per agg tile (128 x AROW)
#define AB 782       // ceil(NA/128)
#define EB 1563      // ceil(NE/128)
#define SMEM_WORDS (6144 + 2 * AGGW + 128)

__global__ __launch_bounds__(256, 2)
void k_fused(const float* __restrict__ b0, const float* __restrict__ b1,
             const float* __restrict__ b2, const float* __restrict__ b3,
             const float* __restrict__ b4, float* __restrict__ out)
{
    extern __shared__ uint32_t dyn[];
    uint32_t* sW   = dyn;                    // 2 x 1536
    uint32_t* sX   = dyn + 3072;             // 2 x 1536
    uint32_t* sAgg = dyn + 6144;             // 2 x 8704
    float*    sSS  = (float*)(dyn + 6144 + 2 * AGGW);  // 128

    const int tid = threadIdx.x;
    const int lane = tid & 31;
    const int warpId = tid >> 5;
    const int warpN = warpId & 1;
    const int warpM = warpId >> 1;
    const int g = lane >> 2;
    const int tg = lane & 3;

    int b = blockIdx.x;
    int kind, mblk;
    if (b < AB) { kind = 0; mblk = b; }
    else if (b < AB + EB) { kind = 1; mblk = b - AB; }
    else { kind = 2; mblk = b - (AB + EB); }
    const int m0 = mblk * 128;
    const int ndst = (kind == 1) ? NE : NA;
    const size_t xRowOff = (kind == 0) ? 0 : (kind == 1) ? (size_t)NA : (size_t)(NA + NE);
    float* osec = out + ((kind == 0) ? 0 : (kind == 1) ? (size_t)NA * DD : (size_t)(NA + NE) * DD);
    const int tA = (kind == 0) ? 2 : (kind == 1) ? 0 : 1;
    const int tB = (kind == 0) ? -1 : (kind == 1) ? 4 : 3;
    const int ntypes = (kind == 0) ? 1 : 2;

    const int lr = tid & 127;
    const bool isW = tid >= 128;

    // ---- phase A: aggregate ALL rows (both types) with edge-batched gathers ----
    {
        int half = lane >> 4;
        int l16 = lane & 15;
        int total = 128 * ntypes;
        for (int rr = warpId * 2 + half; rr < total; rr += 16) {
            int it = rr >> 7;
            int r = rr & 127;
            int t = (it == 0) ? tA : tB;
            int dOff = dst_off_of(t);
            size_t sOff = (t <= 1) ? 0 : (t <= 3) ? (size_t)NA : (size_t)(NA + NE);
            int m = m0 + r;
            float f[8] = {0.f, 0.f, 0.f, 0.f, 0.f, 0.f, 0.f, 0.f};
            int cnt = 0;
            if (m < ndst) {
                int gid = dOff + m;
                int start = __ldg(&g_rowstart[gid]);
                cnt = __ldg(&g_cnt[gid]);
                for (int jb = 0; jb < cnt; jb += 4) {
                    int ss[4];
                    uint4 v[4];
#pragma unroll
                    for (int k = 0; k < 4; k++)
                        ss[k] = (jb + k < cnt) ? __ldg(&g_edge_src[start + jb + k]) : -1;
#pragma unroll
                    for (int k = 0; k < 4; k++) {
                        if (ss[k] >= 0)
                            v[k] = __ldg((const uint4*)(g_xh32 + ((size_t)sOff + ss[k]) * 64 + l16 * 4));
                        else
                            v[k] = make_uint4(0, 0, 0, 0);
                    }
#pragma unroll
                    for (int k = 0; k < 4; k++) {
                        __half2 h; float2 q;
                        h = *(__half2*)&v[k].x; q = __half22float2(h); f[0] += q.x; f[1] += q.y;
                        h = *(__half2*)&v[k].y; q = __half22float2(h); f[2] += q.x; f[3] += q.y;
                        h = *(__half2*)&v[k].z; q = __half22float2(h); f[4] += q.x; f[5] += q.y;
                        h = *(__half2*)&v[k].w; q = __half22float2(h); f[6] += q.x; f[7] += q.y;
                    }
                }
            }
            float inv = 1.0f / (float)(cnt > 1 ? cnt : 1);
            uint4 o;
            __half2 h0 = __floats2half2_rn(f[0] * inv, f[1] * inv); o.x = *(uint32_t*)&h0;
            __half2 h1 = __floats2half2_rn(f[2] * inv, f[3] * inv); o.y = *(uint32_t*)&h1;
            __half2 h2 = __floats2half2_rn(f[4] * inv, f[5] * inv); o.z = *(uint32_t*)&h2;
            __half2 h3 = __floats2half2_rn(f[6] * inv, f[7] * inv); o.w = *(uint32_t*)&h3;
            *(uint4*)(sAgg + it * AGGW + r * AROW + l16 * 4) = o;
        }
    }
    __syncthreads();

    // ---- phase B: per type, K=256 GEMM + epilogue ----
    for (int it = 0; it < ntypes; it++) {
        const int t = (it == 0) ? tA : tB;
        const uint32_t* wbase = g_wh32 + (size_t)t * 16384;
        const uint32_t* aggT = sAgg + it * AGGW;
        const float* bias = (t == 0) ? b0 : (t == 1) ? b1 : (t == 2) ? b2 : (t == 3) ? b3 : b4;

        __syncthreads();                  // prior epilogue's sSS reads complete
        if (tid < 128) sSS[tid] = 0.f;

        float c[4][4][4];
#pragma unroll
        for (int a = 0; a < 4; a++)
#pragma unroll
            for (int bb2 = 0; bb2 < 4; bb2++)
#pragma unroll
                for (int r = 0; r < 4; r++) c[a][bb2][r] = 0.f;

        uint4 st0, st1;
        auto load_stage = [&](int kt) {
            if (!isW) {
                if (kt < 8) {
                    int m = m0 + lr;
                    if (m < ndst) {
                        const uint32_t* src = g_xh32 + ((size_t)(xRowOff + m)) * 64 + kt * 8;
                        st0 = *(const uint4*)src;
                        st1 = *(const uint4*)(src + 4);
                    } else {
                        st0 = make_uint4(0, 0, 0, 0);
                        st1 = st0;
                    }
                }
            } else {
                const uint32_t* src = wbase + ((kt >= 8) ? 8192 : 0) + lr * 64 + (kt & 7) * 8;
                st0 = *(const uint4*)src;
                st1 = *(const uint4*)(src + 4);
            }
        };
        auto store_stage = [&](int buf, int kt) {
            if (!isW) {
                if (kt < 8) {
                    uint32_t* s = sX + buf * 1536 + lr * SROW;
                    *(uint4*)s = st0;
                    *(uint4*)(s + 4) = st1;
                }
            } else {
                uint32_t* s = sW + buf * 1536 + lr * SROW;
                *(uint4*)s = st0;
                *(uint4*)(s + 4) = st1;
            }
        };

        load_stage(0);
        store_stage(0, 0);
        __syncthreads();

        for (int kt = 0; kt < 16; kt++) {
            int cur = kt & 1;
            if (kt < 15) load_stage(kt + 1);

            const uint32_t* sWc = sW + cur * 1536;
            uint32_t Bf[4][2];
            if (kt < 8) {
                const uint32_t* sXc = sX + cur * 1536;
#pragma unroll
                for (int mt = 0; mt < 4; mt++) {
                    int base = (warpM * 32 + mt * 8 + g) * SROW + tg;
                    Bf[mt][0] = sXc[base];
                    Bf[mt][1] = sXc[base + 4];
                }
            } else {
#pragma unroll
                for (int mt = 0; mt < 4; mt++) {
                    int base = (warpM * 32 + mt * 8 + g) * AROW + (kt - 8) * 8 + tg;
                    Bf[mt][0] = aggT[base];
                    Bf[mt][1] = aggT[base + 4];
                }
            }
#pragma unroll
            for (int nt = 0; nt < 4; nt++) {
                int rw = (warpN * 64 + nt * 16 + g) * SROW + tg;
                uint32_t a0 = sWc[rw];
                uint32_t a1 = sWc[rw + 8 * SROW];
                uint32_t a2 = sWc[rw + 4];
                uint32_t a3 = sWc[rw + 8 * SROW + 4];
#pragma unroll
                for (int mt = 0; mt < 4; mt++) {
                    asm volatile(
                        "mma.sync.aligned.m16n8k16.row.col.f32.f16.f16.f32 "
                        "{%0,%1,%2,%3}, {%4,%5,%6,%7}, {%8,%9}, {%0,%1,%2,%3};\n"
                        : "+f"(c[nt][mt][0]), "+f"(c[nt][mt][1]),
                          "+f"(c[nt][mt][2]), "+f"(c[nt][mt][3])
                        : "r"(a0), "r"(a1), "r"(a2), "r"(a3),
                          "r"(Bf[mt][0]), "r"(Bf[mt][1]));
                }
            }

            if (kt < 15) {
                store_stage(cur ^ 1, kt + 1);
                __syncthreads();
            }
        }

        // ---- epilogue: bias, per-row L2 norm, store (it==0) or RMW add (it==1) ----
        float bias_v[4][2];
#pragma unroll
        for (int nt = 0; nt < 4; nt++) {
            int n = warpN * 64 + nt * 16 + g;
            bias_v[nt][0] = __ldg(&bias[n]);
            bias_v[nt][1] = __ldg(&bias[n + 8]);
        }
#pragma unroll
        for (int nt = 0; nt < 4; nt++)
#pragma unroll
            for (int mt = 0; mt < 4; mt++)
#pragma unroll
                for (int r = 0; r < 4; r++)
                    c[nt][mt][r] += bias_v[nt][r >> 1];

        float ps[4][2];
#pragma unroll
        for (int mt = 0; mt < 4; mt++)
#pragma unroll
            for (int j = 0; j < 2; j++) {
                float s = 0.f;
#pragma unroll
                for (int nt = 0; nt < 4; nt++) {
                    float v0 = c[nt][mt][j];
                    float v1 = c[nt][mt][2 + j];
                    s += v0 * v0 + v1 * v1;
                }
                s += __shfl_xor_sync(0xFFFFFFFFu, s, 4);
                s += __shfl_xor_sync(0xFFFFFFFFu, s, 8);
                s += __shfl_xor_sync(0xFFFFFFFFu, s, 16);
                ps[mt][j] = s;
            }
        if (g == 0) {
#pragma unroll
            for (int mt = 0; mt < 4; mt++)
#pragma unroll
                for (int j = 0; j < 2; j++)
                    atomicAdd(&sSS[warpM * 32 + mt * 8 + 2 * tg + j], ps[mt][j]);
        }
        __syncthreads();

#pragma unroll
        for (int mt = 0; mt < 4; mt++) {
#pragma unroll
            for (int j = 0; j < 2; j++) {
                int mloc = warpM * 32 + mt * 8 + 2 * tg + j;
                int m = m0 + mloc;
                if (m >= ndst) continue;
                float nrm = sqrtf(sSS[mloc]);
                float scale = 1.0f / fmaxf(nrm, 1e-12f);
                float* orow = osec + (size_t)m * DD;
#pragma unroll
                for (int nt = 0; nt < 4; nt++) {
#pragma unroll
                    for (int h = 0; h < 2; h++) {
                        int n = warpN * 64 + nt * 16 + g + h * 8;
                        float v = c[nt][mt][2 * h + j] * scale;
                        if (it > 0) v += orow[n];
                        orow[n] = v;
                    }
                }
            }
        }
    }
}

extern "C" void kernel_launch(void* const* d_in, const int* in_sizes, int n_in,
                              void* d_out, int out_size)
{
    const float* xa = (const float*)d_in[0];
    const float* xe = (const float*)d_in[1];
    const float* xf = (const float*)d_in[2];

    const int* si[5];
    const int* di[5];
    for (int t = 0; t < 5; t++) {
        si[t] = (const int*)d_in[3 + 2 * t];
        di[t] = (const int*)d_in[4 + 2 * t];
    }
    const float* wl[5];
    const float* bb[5];
    const float* wr[5];
    for (int t = 0; t < 5; t++) {
        wl[t] = (const float*)d_in[13 + 3 * t];
        bb[t] = (const float*)d_in[14 + 3 * t];
        wr[t] = (const float*)d_in[15 + 3 * t];
    }

    float* out = (float*)d_out;

    // ---- pre-pass: fp32 -> fp16 copies ----
    {
        dim3 gx((NE * 32 + 255) / 256, 3);
        k_tohalf_x<<<gx, 256>>>(xa, xe, xf);
        dim3 gw(16, 10);
        k_tohalf_w<<<gw, 256>>>(wl[0], wr[0], wl[1], wr[1], wl[2], wr[2], wl[3], wr[3], wl[4], wr[4]);
    }

    // ---- batched CSR build ----
    k_zero_cnt<<<(TOTDST + 255) / 256, 256>>>();
    {
        dim3 gh((NEDGE + 255) / 256, 5);
        k_hist<<<gh, 256>>>(di[0], di[1], di[2], di[3], di[4]);
    }
    int nb = (TOTDST + 4095) / 4096;
    k_scan1<<<nb, 1024>>>();
    k_scan2<<<1, 256>>>(nb);
    k_scan3<<<(TOTDST + 255) / 256, 256>>>();
    {
        dim3 gh((NEDGE + 255) / 256, 5);
        k_scatter<<<gh, 256>>>(si[0], si[1], si[2], si[3], si[4],
                               di[0], di[1], di[2], di[3], di[4]);
    }

    // ---- fused aggregate + GEMM + normalize + combine (single launch) ----
    const int SMEM_BYTES = SMEM_WORDS * 4;   // 94,784 B
    cudaFuncSetAttribute(k_fused, cudaFuncAttributeMaxDynamicSharedMemorySize, SMEM_BYTES);
    k_fused<<<AB + EB + AB, 256, SMEM_BYTES>>>(bb[0], bb[1], bb[2], bb[3], bb[4], out);
}

// round 9
// speedup vs baseline: 2.8109x; 1.0873x over previous
#include <cuda_runtime.h>
#include <cuda_fp16.h>
#include <cstdint>

#define NA 100000
#define NE 200000
#define NF 100000
#define DD 128
#define NEDGE 400000
#define TOTDST 700000
#define TOTEDGE 2000000
#define TOTSRC 400000   // xa + xe + xf rows

// ---------------- scratch (device globals: allocation-free) ----------------
__device__ uint32_t g_xh32[(size_t)TOTSRC * 64];   // 102.4 MB  [xa|xe|xf] rows x 128 halves
__device__ uint32_t g_wh32[5 * 2 * 8192];          // 5 types x {wl,wr} x 128x128 halves
__device__ int   g_cnt[TOTDST];
__device__ int   g_rowstart[TOTDST];
__device__ int   g_cursor[TOTDST];
__device__ int   g_edge_src[TOTEDGE];
__device__ int   g_bsums[256];

// ---------------- fp32 -> fp16 pre-pass ----------------
__global__ void k_tohalf_x(const float* __restrict__ xa, const float* __restrict__ xe,
                           const float* __restrict__ xf) {
    int y = blockIdx.y;
    const float* src = (y == 0) ? xa : (y == 1) ? xe : xf;
    int rows = (y == 1) ? NE : NA;
    size_t dstoff = (y == 0) ? 0 : (y == 1) ? (size_t)NA * 32 : (size_t)(NA + NE) * 32;
    int n4 = rows * 32;
    int i = blockIdx.x * 256 + threadIdx.x;
    if (i >= n4) return;
    float4 v = ((const float4*)src)[i];
    __half2 a = __floats2half2_rn(v.x, v.y);
    __half2 b = __floats2half2_rn(v.z, v.w);
    uint32_t* d = g_xh32 + dstoff * 2 + (size_t)i * 2;
    d[0] = *(uint32_t*)&a;
    d[1] = *(uint32_t*)&b;
}

__global__ void k_tohalf_w(const float* p0, const float* p1, const float* p2, const float* p3,
                           const float* p4, const float* p5, const float* p6, const float* p7,
                           const float* p8, const float* p9) {
    int y = blockIdx.y;
    const float* src = (y == 0) ? p0 : (y == 1) ? p1 : (y == 2) ? p2 : (y == 3) ? p3 :
                       (y == 4) ? p4 : (y == 5) ? p5 : (y == 6) ? p6 : (y == 7) ? p7 :
                       (y == 8) ? p8 : p9;
    int i = blockIdx.x * 256 + threadIdx.x;
    if (i >= 4096) return;
    float4 v = ((const float4*)src)[i];
    __half2 a = __floats2half2_rn(v.x, v.y);
    __half2 b = __floats2half2_rn(v.z, v.w);
    uint32_t* d = g_wh32 + (size_t)y * 8192 + (size_t)i * 2;
    d[0] = *(uint32_t*)&a;
    d[1] = *(uint32_t*)&b;
}

// ---------------- batched CSR build ----------------
__global__ void k_zero_cnt() {
    int i = blockIdx.x * blockDim.x + threadIdx.x;
    if (i < TOTDST) g_cnt[i] = 0;
}

__device__ __forceinline__ int dst_off_of(int t) {
    return (t == 0) ? 0 : (t == 1) ? 200000 : (t == 2) ? 300000 : (t == 3) ? 400000 : 500000;
}

__global__ void k_hist(const int* d0, const int* d1, const int* d2, const int* d3, const int* d4) {
    int e = blockIdx.x * 256 + threadIdx.x;
    if (e >= NEDGE) return;
    int t = blockIdx.y;
    const int* di = (t == 0) ? d0 : (t == 1) ? d1 : (t == 2) ? d2 : (t == 3) ? d3 : d4;
    atomicAdd(&g_cnt[dst_off_of(t) + di[e]], 1);
}

__global__ void k_scan1() {
    __shared__ int s[1024];
    int t = threadIdx.x;
    int base = blockIdx.x * 4096;
    int v[4];
    int sum = 0;
#pragma unroll
    for (int j = 0; j < 4; j++) {
        int idx = base + t * 4 + j;
        v[j] = (idx < TOTDST) ? g_cnt[idx] : 0;
        sum += v[j];
    }
    s[t] = sum;
    __syncthreads();
    for (int off = 1; off < 1024; off <<= 1) {
        int x = (t >= off) ? s[t - off] : 0;
        __syncthreads();
        if (t >= off) s[t] += x;
        __syncthreads();
    }
    int excl = s[t] - sum;
    if (t == 1023) g_bsums[blockIdx.x] = s[1023];
    int run = excl;
#pragma unroll
    for (int j = 0; j < 4; j++) {
        int idx = base + t * 4 + j;
        if (idx < TOTDST) g_rowstart[idx] = run;
        run += v[j];
    }
}

__global__ void k_scan2(int nb) {
    __shared__ int s[256];
    int t = threadIdx.x;
    int v = (t < nb) ? g_bsums[t] : 0;
    s[t] = v;
    __syncthreads();
    for (int off = 1; off < 256; off <<= 1) {
        int x = (t >= off) ? s[t - off] : 0;
        __syncthreads();
        s[t] += x;
        __syncthreads();
    }
    if (t < nb) g_bsums[t] = s[t] - v;
}

__global__ void k_scan3() {
    int i = blockIdx.x * blockDim.x + threadIdx.x;
    if (i < TOTDST) {
        int r = g_rowstart[i] + g_bsums[i >> 12];
        g_rowstart[i] = r;
        g_cursor[i] = r;
    }
}

__global__ void k_scatter(const int* s0, const int* s1, const int* s2, const int* s3, const int* s4,
                          const int* d0, const int* d1, const int* d2, const int* d3, const int* d4) {
    int e = blockIdx.x * 256 + threadIdx.x;
    if (e >= NEDGE) return;
    int t = blockIdx.y;
    const int* si = (t == 0) ? s0 : (t == 1) ? s1 : (t == 2) ? s2 : (t == 3) ? s3 : s4;
    const int* di = (t == 0) ? d0 : (t == 1) ? d1 : (t == 2) ? d2 : (t == 3) ? d3 : d4;
    int d = dst_off_of(t) + di[e];
    int p = atomicAdd(&g_cursor[d], 1);
    g_edge_src[p] = si[e];
}

// ---------------- fused aggregate + dual-type GEMM + normalize + combine ----------------
// Phase A aggregates BOTH edge types' 128 dst rows with 4 rows in flight per warp
// (8 lanes x 32B per row) and unroll-4 edge batches -> 8 outstanding LDG.128/lane.
// Phase B runs the two K=256 GEMMs back-to-back.

#define SROW 12      // staged-tile row stride (words)
#define AROW 68      // agg tile row stride (words); 68 mod 32 == 4 -> conflict-free frags
#define AGGW 8704    // words per agg tile (128 x AROW)
#define AB 782       // ceil(NA/128)
#define EB 1563      // ceil(NE/128)
#define SMEM_WORDS (6144 + 2 * AGGW + 128)

__global__ __launch_bounds__(256, 2)
void k_fused(const float* __restrict__ b0, const float* __restrict__ b1,
             const float* __restrict__ b2, const float* __restrict__ b3,
             const float* __restrict__ b4, float* __restrict__ out)
{
    extern __shared__ uint32_t dyn[];
    uint32_t* sW   = dyn;                    // 2 x 1536
    uint32_t* sX   = dyn + 3072;             // 2 x 1536
    uint32_t* sAgg = dyn + 6144;             // 2 x 8704
    float*    sSS  = (float*)(dyn + 6144 + 2 * AGGW);  // 128

    const int tid = threadIdx.x;
    const int lane = tid & 31;
    const int warpId = tid >> 5;
    const int warpN = warpId & 1;
    const int warpM = warpId >> 1;
    const int g = lane >> 2;
    const int tg = lane & 3;

    int b = blockIdx.x;
    int kind, mblk;
    if (b < AB) { kind = 0; mblk = b; }
    else if (b < AB + EB) { kind = 1; mblk = b - AB; }
    else { kind = 2; mblk = b - (AB + EB); }
    const int m0 = mblk * 128;
    const int ndst = (kind == 1) ? NE : NA;
    const size_t xRowOff = (kind == 0) ? 0 : (kind == 1) ? (size_t)NA : (size_t)(NA + NE);
    float* osec = out + ((kind == 0) ? 0 : (kind == 1) ? (size_t)NA * DD : (size_t)(NA + NE) * DD);
    const int tA = (kind == 0) ? 2 : (kind == 1) ? 0 : 1;
    const int tB = (kind == 0) ? -1 : (kind == 1) ? 4 : 3;
    const int ntypes = (kind == 0) ? 1 : 2;

    const int lr = tid & 127;
    const bool isW = tid >= 128;

    // ---- phase A: aggregate (both types); 4 rows/warp, 8 lanes x 32B per row ----
    {
        int rowsel = lane >> 3;   // 0..3: which of the warp's 4 concurrent rows
        int l8 = lane & 7;        // 0..7: 32B slice within the 256B row
        int total = 128 * ntypes;
        for (int rr = warpId * 4 + rowsel; rr < total; rr += 32) {
            int it = rr >> 7;
            int r = rr & 127;
            int t = (it == 0) ? tA : tB;
            int dOff = dst_off_of(t);
            size_t sOff = (t <= 1) ? 0 : (t <= 3) ? (size_t)NA : (size_t)(NA + NE);
            int m = m0 + r;
            float f[16];
#pragma unroll
            for (int q = 0; q < 16; q++) f[q] = 0.f;
            int cnt = 0;
            if (m < ndst) {
                int gid = dOff + m;
                int start = __ldg(&g_rowstart[gid]);
                cnt = __ldg(&g_cnt[gid]);
                for (int jb = 0; jb < cnt; jb += 4) {
                    int ss[4];
                    uint4 v0[4], v1[4];
#pragma unroll
                    for (int k = 0; k < 4; k++)
                        ss[k] = (jb + k < cnt) ? __ldg(&g_edge_src[start + jb + k]) : -1;
#pragma unroll
                    for (int k = 0; k < 4; k++) {
                        if (ss[k] >= 0) {
                            const uint4* p = (const uint4*)(g_xh32 + ((size_t)sOff + ss[k]) * 64 + l8 * 8);
                            v0[k] = __ldg(p);
                            v1[k] = __ldg(p + 1);
                        } else {
                            v0[k] = make_uint4(0, 0, 0, 0);
                            v1[k] = v0[k];
                        }
                    }
#pragma unroll
                    for (int k = 0; k < 4; k++) {
                        __half2 h; float2 q;
                        h = *(__half2*)&v0[k].x; q = __half22float2(h); f[0]  += q.x; f[1]  += q.y;
                        h = *(__half2*)&v0[k].y; q = __half22float2(h); f[2]  += q.x; f[3]  += q.y;
                        h = *(__half2*)&v0[k].z; q = __half22float2(h); f[4]  += q.x; f[5]  += q.y;
                        h = *(__half2*)&v0[k].w; q = __half22float2(h); f[6]  += q.x; f[7]  += q.y;
                        h = *(__half2*)&v1[k].x; q = __half22float2(h); f[8]  += q.x; f[9]  += q.y;
                        h = *(__half2*)&v1[k].y; q = __half22float2(h); f[10] += q.x; f[11] += q.y;
                        h = *(__half2*)&v1[k].z; q = __half22float2(h); f[12] += q.x; f[13] += q.y;
                        h = *(__half2*)&v1[k].w; q = __half22float2(h); f[14] += q.x; f[15] += q.y;
                    }
                }
            }
            float inv = 1.0f / (float)(cnt > 1 ? cnt : 1);
            uint4 o0, o1;
            {
                __half2 h0 = __floats2half2_rn(f[0] * inv,  f[1] * inv);  o0.x = *(uint32_t*)&h0;
                __half2 h1 = __floats2half2_rn(f[2] * inv,  f[3] * inv);  o0.y = *(uint32_t*)&h1;
                __half2 h2 = __floats2half2_rn(f[4] * inv,  f[5] * inv);  o0.z = *(uint32_t*)&h2;
                __half2 h3 = __floats2half2_rn(f[6] * inv,  f[7] * inv);  o0.w = *(uint32_t*)&h3;
                __half2 h4 = __floats2half2_rn(f[8] * inv,  f[9] * inv);  o1.x = *(uint32_t*)&h4;
                __half2 h5 = __floats2half2_rn(f[10] * inv, f[11] * inv); o1.y = *(uint32_t*)&h5;
                __half2 h6 = __floats2half2_rn(f[12] * inv, f[13] * inv); o1.z = *(uint32_t*)&h6;
                __half2 h7 = __floats2half2_rn(f[14] * inv, f[15] * inv); o1.w = *(uint32_t*)&h7;
            }
            uint4* dst = (uint4*)(sAgg + it * AGGW + r * AROW + l8 * 8);
            dst[0] = o0;
            dst[1] = o1;
        }
    }
    __syncthreads();

    // ---- phase B: per type, K=256 GEMM + epilogue ----
    for (int it = 0; it < ntypes; it++) {
        const int t = (it == 0) ? tA : tB;
        const uint32_t* wbase = g_wh32 + (size_t)t * 16384;
        const uint32_t* aggT = sAgg + it * AGGW;
        const float* bias = (t == 0) ? b0 : (t == 1) ? b1 : (t == 2) ? b2 : (t == 3) ? b3 : b4;

        __syncthreads();                  // prior epilogue's sSS reads complete
        if (tid < 128) sSS[tid] = 0.f;

        float c[4][4][4];
#pragma unroll
        for (int a = 0; a < 4; a++)
#pragma unroll
            for (int bb2 = 0; bb2 < 4; bb2++)
#pragma unroll
                for (int r = 0; r < 4; r++) c[a][bb2][r] = 0.f;

        uint4 st0, st1;
        auto load_stage = [&](int kt) {
            if (!isW) {
                if (kt < 8) {
                    int m = m0 + lr;
                    if (m < ndst) {
                        const uint32_t* src = g_xh32 + ((size_t)(xRowOff + m)) * 64 + kt * 8;
                        st0 = *(const uint4*)src;
                        st1 = *(const uint4*)(src + 4);
                    } else {
                        st0 = make_uint4(0, 0, 0, 0);
                        st1 = st0;
                    }
                }
            } else {
                const uint32_t* src = wbase + ((kt >= 8) ? 8192 : 0) + lr * 64 + (kt & 7) * 8;
                st0 = *(const uint4*)src;
                st1 = *(const uint4*)(src + 4);
            }
        };
        auto store_stage = [&](int buf, int kt) {
            if (!isW) {
                if (kt < 8) {
                    uint32_t* s = sX + buf * 1536 + lr * SROW;
                    *(uint4*)s = st0;
                    *(uint4*)(s + 4) = st1;
                }
            } else {
                uint32_t* s = sW + buf * 1536 + lr * SROW;
                *(uint4*)s = st0;
                *(uint4*)(s + 4) = st1;
            }
        };

        load_stage(0);
        store_stage(0, 0);
        __syncthreads();

        for (int kt = 0; kt < 16; kt++) {
            int cur = kt & 1;
            if (kt < 15) load_stage(kt + 1);

            const uint32_t* sWc = sW + cur * 1536;
            uint32_t Bf[4][2];
            if (kt < 8) {
                const uint32_t* sXc = sX + cur * 1536;
#pragma unroll
                for (int mt = 0; mt < 4; mt++) {
                    int base = (warpM * 32 + mt * 8 + g) * SROW + tg;
                    Bf[mt][0] = sXc[base];
                    Bf[mt][1] = sXc[base + 4];
                }
            } else {
#pragma unroll
                for (int mt = 0; mt < 4; mt++) {
                    int base = (warpM * 32 + mt * 8 + g) * AROW + (kt - 8) * 8 + tg;
                    Bf[mt][0] = aggT[base];
                    Bf[mt][1] = aggT[base + 4];
                }
            }
#pragma unroll
            for (int nt = 0; nt < 4; nt++) {
                int rw = (warpN * 64 + nt * 16 + g) * SROW + tg;
                uint32_t a0 = sWc[rw];
                uint32_t a1 = sWc[rw + 8 * SROW];
                uint32_t a2 = sWc[rw + 4];
                uint32_t a3 = sWc[rw + 8 * SROW + 4];
#pragma unroll
                for (int mt = 0; mt < 4; mt++) {
                    asm volatile(
                        "mma.sync.aligned.m16n8k16.row.col.f32.f16.f16.f32 "
                        "{%0,%1,%2,%3}, {%4,%5,%6,%7}, {%8,%9}, {%0,%1,%2,%3};\n"
                        : "+f"(c[nt][mt][0]), "+f"(c[nt][mt][1]),
                          "+f"(c[nt][mt][2]), "+f"(c[nt][mt][3])
                        : "r"(a0), "r"(a1), "r"(a2), "r"(a3),
                          "r"(Bf[mt][0]), "r"(Bf[mt][1]));
                }
            }

            if (kt < 15) {
                store_stage(cur ^ 1, kt + 1);
                __syncthreads();
            }
        }

        // ---- epilogue: bias, per-row L2 norm, store (it==0) or RMW add (it==1) ----
        float bias_v[4][2];
#pragma unroll
        for (int nt = 0; nt < 4; nt++) {
            int n = warpN * 64 + nt * 16 + g;
            bias_v[nt][0] = __ldg(&bias[n]);
            bias_v[nt][1] = __ldg(&bias[n + 8]);
        }
#pragma unroll
        for (int nt = 0; nt < 4; nt++)
#pragma unroll
            for (int mt = 0; mt < 4; mt++)
#pragma unroll
                for (int r = 0; r < 4; r++)
                    c[nt][mt][r] += bias_v[nt][r >> 1];

        float ps[4][2];
#pragma unroll
        for (int mt = 0; mt < 4; mt++)
#pragma unroll
            for (int j = 0; j < 2; j++) {
                float s = 0.f;
#pragma unroll
                for (int nt = 0; nt < 4; nt++) {
                    float v0 = c[nt][mt][j];
                    float v1 = c[nt][mt][2 + j];
                    s += v0 * v0 + v1 * v1;
                }
                s += __shfl_xor_sync(0xFFFFFFFFu, s, 4);
                s += __shfl_xor_sync(0xFFFFFFFFu, s, 8);
                s += __shfl_xor_sync(0xFFFFFFFFu, s, 16);
                ps[mt][j] = s;
            }
        if (g == 0) {
#pragma unroll
            for (int mt = 0; mt < 4; mt++)
#pragma unroll
                for (int j = 0; j < 2; j++)
                    atomicAdd(&sSS[warpM * 32 + mt * 8 + 2 * tg + j], ps[mt][j]);
        }
        __syncthreads();

#pragma unroll
        for (int mt = 0; mt < 4; mt++) {
#pragma unroll
            for (int j = 0; j < 2; j++) {
                int mloc = warpM * 32 + mt * 8 + 2 * tg + j;
                int m = m0 + mloc;
                if (m >= ndst) continue;
                float nrm = sqrtf(sSS[mloc]);
                float scale = 1.0f / fmaxf(nrm, 1e-12f);
                float* orow = osec + (size_t)m * DD;
#pragma unroll
                for (int nt = 0; nt < 4; nt++) {
#pragma unroll
                    for (int h = 0; h < 2; h++) {
                        int n = warpN * 64 + nt * 16 + g + h * 8;
                        float v = c[nt][mt][2 * h + j] * scale;
                        if (it > 0) v += orow[n];
                        orow[n] = v;
                    }
                }
            }
        }
    }
}

extern "C" void kernel_launch(void* const* d_in, const int* in_sizes, int n_in,
                              void* d_out, int out_size)
{
    const float* xa = (const float*)d_in[0];
    const float* xe = (const float*)d_in[1];
    const float* xf = (const float*)d_in[2];

    const int* si[5];
    const int* di[5];
    for (int t = 0; t < 5; t++) {
        si[t] = (const int*)d_in[3 + 2 * t];
        di[t] = (const int*)d_in[4 + 2 * t];
    }
    const float* wl[5];
    const float* bb[5];
    const float* wr[5];
    for (int t = 0; t < 5; t++) {
        wl[t] = (const float*)d_in[13 + 3 * t];
        bb[t] = (const float*)d_in[14 + 3 * t];
        wr[t] = (const float*)d_in[15 + 3 * t];
    }

    float* out = (float*)d_out;

    // ---- pre-pass: fp32 -> fp16 copies ----
    {
        dim3 gx((NE * 32 + 255) / 256, 3);
        k_tohalf_x<<<gx, 256>>>(xa, xe, xf);
        dim3 gw(16, 10);
        k_tohalf_w<<<gw, 256>>>(wl[0], wr[0], wl[1], wr[1], wl[2], wr[2], wl[3], wr[3], wl[4], wr[4]);
    }

    // ---- batched CSR build ----
    k_zero_cnt<<<(TOTDST + 255) / 256, 256>>>();
    {
        dim3 gh((NEDGE + 255) / 256, 5);
        k_hist<<<gh, 256>>>(di[0], di[1], di[2], di[3], di[4]);
    }
    int nb = (TOTDST + 4095) / 4096;
    k_scan1<<<nb, 1024>>>();
    k_scan2<<<1, 256>>>(nb);
    k_scan3<<<(TOTDST + 255) / 256, 256>>>();
    {
        dim3 gh((NEDGE + 255) / 256, 5);
        k_scatter<<<gh, 256>>>(si[0], si[1], si[2], si[3], si[4],
                               di[0], di[1], di[2], di[3], di[4]);
    }

    // ---- fused aggregate + GEMM + normalize + combine (single launch) ----
    const int SMEM_BYTES = SMEM_WORDS * 4;   // 94,784 B
    cudaFuncSetAttribute(k_fused, cudaFuncAttributeMaxDynamicSharedMemorySize, SMEM_BYTES);
    k_fused<<<AB + EB + AB, 256, SMEM_BYTES>>>(bb[0], bb[1], bb[2], bb[3], bb[4], out);
}